// round 1
// baseline (speedup 1.0000x reference)
#include <cuda_runtime.h>
#include <cstdint>

// Problem constants
constexpr int Bc   = 4;
constexpr int Sseq = 2048;
constexpr int Dm   = 1024;
constexpr int Hn   = 16;
constexpr int DHc  = 64;
constexpr int Mrows = Bc * Sseq;     // 8192

// Device-global scratch (no cudaMalloc allowed)
__device__ float g_Qh[(size_t)Bc * Hn * Sseq * DHc];  // [B,H,S,DH]
__device__ float g_Kh[(size_t)Bc * Hn * Sseq * DHc];  // [B,H,S,DH] (quirk layout)
__device__ float g_Vh[(size_t)Bc * Hn * Sseq * DHc];  // [B,H,S,DH]
__device__ float g_O [(size_t)Mrows * Dm];            // [B*S, D]

// ---------------------------------------------------------------------------
// Tiled SGEMM: C[m,n] = sum_k A[m,k] * W[n,k] + bias[n]
// MODE 0: A = g_O (symbol), plain write to Cout            (final projection)
// MODE 1: A = param, scatter to g_Qh   (h = n>>6, d = n&63)
// MODE 2: A = param, scatter to g_Kh   (h = n&15, d = n>>4)  <- K view quirk
// MODE 3: A = param, scatter to g_Vh   (h = n>>6, d = n&63)
// ---------------------------------------------------------------------------
constexpr int GBM = 128, GBN = 128, GBK = 16;

template <int MODE>
__global__ __launch_bounds__(256, 2)
void gemm_kernel(const float* __restrict__ A,
                 const float* __restrict__ W,
                 const float* __restrict__ bias,
                 float* __restrict__ Cout)
{
    __shared__ float As[GBK][GBM + 4];   // [k][m]
    __shared__ float Bs[GBK][GBN + 4];   // [k][n]

    const int bm  = blockIdx.y * GBM;
    const int bn  = blockIdx.x * GBN;
    const int tid = threadIdx.x;
    const int tx  = tid & 15;
    const int ty  = tid >> 4;

    const float* __restrict__ Ap = (MODE == 0) ? (const float*)g_O : A;

    float acc[8][8];
#pragma unroll
    for (int i = 0; i < 8; i++)
#pragma unroll
        for (int j = 0; j < 8; j++) acc[i][j] = 0.f;

    for (int k0 = 0; k0 < Dm; k0 += GBK) {
#pragma unroll
        for (int i = 0; i < 2; i++) {
            int f   = tid + i * 256;          // 512 float4 per tile
            int row = f >> 2;
            int c4  = (f & 3) << 2;
            float4 a = *(const float4*)(Ap + (size_t)(bm + row) * Dm + k0 + c4);
            As[c4 + 0][row] = a.x; As[c4 + 1][row] = a.y;
            As[c4 + 2][row] = a.z; As[c4 + 3][row] = a.w;
            float4 b = *(const float4*)(W + (size_t)(bn + row) * Dm + k0 + c4);
            Bs[c4 + 0][row] = b.x; Bs[c4 + 1][row] = b.y;
            Bs[c4 + 2][row] = b.z; Bs[c4 + 3][row] = b.w;
        }
        __syncthreads();

#pragma unroll
        for (int k = 0; k < GBK; k++) {
            float a[8], b[8];
            *(float4*)(a)     = *(const float4*)&As[k][ty * 8];
            *(float4*)(a + 4) = *(const float4*)&As[k][ty * 8 + 4];
            *(float4*)(b)     = *(const float4*)&Bs[k][tx * 8];
            *(float4*)(b + 4) = *(const float4*)&Bs[k][tx * 8 + 4];
#pragma unroll
            for (int i = 0; i < 8; i++)
#pragma unroll
                for (int j = 0; j < 8; j++)
                    acc[i][j] = fmaf(a[i], b[j], acc[i][j]);
        }
        __syncthreads();
    }

    // epilogue
#pragma unroll
    for (int i = 0; i < 8; i++) {
        const int m = bm + ty * 8 + i;
        const int bb = m >> 11;          // m / 2048
        const int ss = m & 2047;
#pragma unroll
        for (int j = 0; j < 8; j++) {
            const int n = bn + tx * 8 + j;
            const float v = acc[i][j] + __ldg(&bias[n]);
            if (MODE == 0) {
                Cout[(size_t)m * Dm + n] = v;
            } else if (MODE == 1) {
                g_Qh[(((size_t)(bb * Hn + (n >> 6)) * Sseq + ss) << 6) + (n & 63)] = v;
            } else if (MODE == 2) {
                g_Kh[(((size_t)(bb * Hn + (n & 15)) * Sseq + ss) << 6) + (n >> 4)] = v;
            } else {
                g_Vh[(((size_t)(bb * Hn + (n >> 6)) * Sseq + ss) << 6) + (n & 63)] = v;
            }
        }
    }
}

// ---------------------------------------------------------------------------
// Flash attention, causal, fp32. Block = 256 threads handles a 64-query tile
// for one (b,h). Online softmax; S and PV GEMMs through shared memory.
// ---------------------------------------------------------------------------
constexpr int QS = 68;   // smem row stride (floats), keeps float4 alignment

__global__ __launch_bounds__(256, 2)
void attn_kernel()
{
    extern __shared__ float sm[];
    float* Qs = sm;                 // [64][QS], [d][r], pre-scaled by 1/8
    float* Ks = Qs + 64 * QS;       // [64][QS], [d][s]
    float* Vs = Ks + 64 * QS;       // [64][QS], [s][c]
    float* Ps = Vs + 64 * QS;       // [64][QS], [s][r]

    const int qt  = blockIdx.x;     // query tile 0..31
    const int bh  = blockIdx.y;     // 0..63
    const int tid = threadIdx.x;
    const int tx  = tid & 15;
    const int ty  = tid >> 4;
    const int r0  = ty * 4;
    const int c0  = tx * 4;

    const size_t headOff = (size_t)bh * Sseq * DHc;
    const float* __restrict__ Qb = g_Qh + headOff + (size_t)qt * 64 * DHc;
    const float scale = 0.125f;     // 1/sqrt(64)

    // load Q tile, transpose to [d][r], fold in softmax scale
#pragma unroll
    for (int i = 0; i < 4; i++) {
        int f  = tid + i * 256;
        int r  = f >> 4;
        int d4 = (f & 15) << 2;
        float4 q = *(const float4*)(Qb + r * DHc + d4);
        Qs[(d4 + 0) * QS + r] = q.x * scale;
        Qs[(d4 + 1) * QS + r] = q.y * scale;
        Qs[(d4 + 2) * QS + r] = q.z * scale;
        Qs[(d4 + 3) * QS + r] = q.w * scale;
    }

    float m_run[4], l_run[4], Oacc[4][4];
#pragma unroll
    for (int i = 0; i < 4; i++) {
        m_run[i] = -1e30f;
        l_run[i] = 0.f;
#pragma unroll
        for (int j = 0; j < 4; j++) Oacc[i][j] = 0.f;
    }

    for (int j = 0; j <= qt; j++) {
        __syncthreads();   // prior readers of Ks/Vs/Ps done
        const float* __restrict__ Kb = g_Kh + headOff + (size_t)j * 64 * DHc;
        const float* __restrict__ Vb = g_Vh + headOff + (size_t)j * 64 * DHc;
#pragma unroll
        for (int i = 0; i < 4; i++) {
            int f  = tid + i * 256;
            int r  = f >> 4;
            int d4 = (f & 15) << 2;
            float4 k = *(const float4*)(Kb + r * DHc + d4);
            Ks[(d4 + 0) * QS + r] = k.x;
            Ks[(d4 + 1) * QS + r] = k.y;
            Ks[(d4 + 2) * QS + r] = k.z;
            Ks[(d4 + 3) * QS + r] = k.w;
            float4 v = *(const float4*)(Vb + r * DHc + d4);
            *(float4*)(Vs + r * QS + d4) = v;
        }
        __syncthreads();

        // scores: sc[i][jj] = sum_d Qs[d][r0+i] * Ks[d][c0+jj]  (Q pre-scaled)
        float sc[4][4];
#pragma unroll
        for (int i = 0; i < 4; i++)
#pragma unroll
            for (int jj = 0; jj < 4; jj++) sc[i][jj] = 0.f;

#pragma unroll 16
        for (int d = 0; d < 64; d++) {
            float4 qv = *(const float4*)(Qs + d * QS + r0);
            float4 kv = *(const float4*)(Ks + d * QS + c0);
            float qa[4] = {qv.x, qv.y, qv.z, qv.w};
            float kb[4] = {kv.x, kv.y, kv.z, kv.w};
#pragma unroll
            for (int i = 0; i < 4; i++)
#pragma unroll
                for (int jj = 0; jj < 4; jj++)
                    sc[i][jj] = fmaf(qa[i], kb[jj], sc[i][jj]);
        }

        if (j == qt) {   // causal mask, diagonal tile only
#pragma unroll
            for (int i = 0; i < 4; i++)
#pragma unroll
                for (int jj = 0; jj < 4; jj++)
                    if (c0 + jj > r0 + i) sc[i][jj] = -1e30f;
        }

        // online softmax update per row
#pragma unroll
        for (int i = 0; i < 4; i++) {
            float v = fmaxf(fmaxf(sc[i][0], sc[i][1]), fmaxf(sc[i][2], sc[i][3]));
#pragma unroll
            for (int off = 8; off >= 1; off >>= 1)
                v = fmaxf(v, __shfl_xor_sync(0xffffffffu, v, off, 16));
            const float mnew  = fmaxf(m_run[i], v);
            const float alpha = __expf(m_run[i] - mnew);
            m_run[i] = mnew;

            float p0 = __expf(sc[i][0] - mnew);
            float p1 = __expf(sc[i][1] - mnew);
            float p2 = __expf(sc[i][2] - mnew);
            float p3 = __expf(sc[i][3] - mnew);
            float rs = (p0 + p1) + (p2 + p3);
#pragma unroll
            for (int off = 8; off >= 1; off >>= 1)
                rs += __shfl_xor_sync(0xffffffffu, rs, off, 16);
            l_run[i] = l_run[i] * alpha + rs;
#pragma unroll
            for (int jj = 0; jj < 4; jj++) Oacc[i][jj] *= alpha;

            Ps[(c0 + 0) * QS + r0 + i] = p0;
            Ps[(c0 + 1) * QS + r0 + i] = p1;
            Ps[(c0 + 2) * QS + r0 + i] = p2;
            Ps[(c0 + 3) * QS + r0 + i] = p3;
        }
        __syncthreads();

        // O += P @ V : Oacc[i][jj] += sum_s Ps[s][r0+i] * Vs[s][c0+jj]
#pragma unroll 16
        for (int s = 0; s < 64; s++) {
            float4 pv = *(const float4*)(Ps + s * QS + r0);
            float4 vv = *(const float4*)(Vs + s * QS + c0);
            float pa[4] = {pv.x, pv.y, pv.z, pv.w};
            float vb[4] = {vv.x, vv.y, vv.z, vv.w};
#pragma unroll
            for (int i = 0; i < 4; i++)
#pragma unroll
                for (int jj = 0; jj < 4; jj++)
                    Oacc[i][jj] = fmaf(pa[i], vb[jj], Oacc[i][jj]);
        }
    }

    // epilogue: normalize and write back to [B,S,D] layout
    const int bb = bh >> 4;
    const int hh = bh & 15;
#pragma unroll
    for (int i = 0; i < 4; i++) {
        const float inv = 1.0f / l_run[i];
        const int qrow  = qt * 64 + r0 + i;
        float4 o;
        o.x = Oacc[i][0] * inv;
        o.y = Oacc[i][1] * inv;
        o.z = Oacc[i][2] * inv;
        o.w = Oacc[i][3] * inv;
        *(float4*)(g_O + (size_t)(bb * Sseq + qrow) * Dm + hh * DHc + c0) = o;
    }
}

// ---------------------------------------------------------------------------
// Launch
// ---------------------------------------------------------------------------
extern "C" void kernel_launch(void* const* d_in, const int* in_sizes, int n_in,
                              void* d_out, int out_size)
{
    const float* x  = (const float*)d_in[0];
    const float* Wq = (const float*)d_in[1];
    const float* bq = (const float*)d_in[2];
    const float* Wk = (const float*)d_in[3];
    const float* bk = (const float*)d_in[4];
    const float* Wv = (const float*)d_in[5];
    const float* bv = (const float*)d_in[6];
    const float* Wp = (const float*)d_in[7];
    const float* bp = (const float*)d_in[8];
    float* out = (float*)d_out;

    const dim3 gg(Dm / GBN, Mrows / GBM);   // (8, 64)

    gemm_kernel<1><<<gg, 256>>>(x, Wq, bq, nullptr);
    gemm_kernel<2><<<gg, 256>>>(x, Wk, bk, nullptr);
    gemm_kernel<3><<<gg, 256>>>(x, Wv, bv, nullptr);

    const int smem = 4 * 64 * QS * (int)sizeof(float);  // 69,632 B
    cudaFuncSetAttribute(attn_kernel, cudaFuncAttributeMaxDynamicSharedMemorySize, smem);
    attn_kernel<<<dim3(Sseq / 64, Bc * Hn), 256, smem>>>();

    gemm_kernel<0><<<gg, 256>>>(nullptr, Wp, bp, out);
}

// round 3
// speedup vs baseline: 1.5465x; 1.5465x over previous
#include <cuda_runtime.h>
#include <cuda_bf16.h>
#include <cstdint>

// ---------------------------------------------------------------------------
// Problem constants
// ---------------------------------------------------------------------------
constexpr int Bc   = 4;
constexpr int Sseq = 2048;
constexpr int Dm   = 1024;
constexpr int Hn   = 16;
constexpr int DHc  = 64;
constexpr int Mrows = Bc * Sseq;     // 8192

// Device-global scratch (no cudaMalloc allowed)
__device__ float g_Qh[(size_t)Bc * Hn * Sseq * DHc];  // [B,H,S,DH]
__device__ float g_Kh[(size_t)Bc * Hn * Sseq * DHc];  // [B,H,S,DH] (quirk layout)
__device__ float g_Vh[(size_t)Bc * Hn * Sseq * DHc];  // [B,H,S,DH]
__device__ float g_O [(size_t)Mrows * Dm];            // [B*S, D]

// ---------------------------------------------------------------------------
// Helpers: shared addr, ldmatrix, mma.sync (all baseline sm_80+ — no "a" insts)
// ---------------------------------------------------------------------------
static __device__ __forceinline__ uint32_t smem_u32(const void* p) {
    uint32_t a;
    asm("{ .reg .u64 t; cvta.to.shared.u64 t, %1; cvt.u32.u64 %0, t; }"
        : "=r"(a) : "l"(p));
    return a;
}

static __device__ __forceinline__ void ldmx4(uint32_t* r, uint32_t addr) {
    asm volatile("ldmatrix.sync.aligned.m8n8.x4.shared.b16 {%0,%1,%2,%3}, [%4];"
        : "=r"(r[0]), "=r"(r[1]), "=r"(r[2]), "=r"(r[3]) : "r"(addr));
}

static __device__ __forceinline__ void mma_bf16(float* c, const uint32_t* a, const uint32_t* b) {
    asm volatile(
        "mma.sync.aligned.m16n8k16.row.col.f32.bf16.bf16.f32 "
        "{%0,%1,%2,%3}, {%4,%5,%6,%7}, {%8,%9}, {%0,%1,%2,%3};"
        : "+f"(c[0]), "+f"(c[1]), "+f"(c[2]), "+f"(c[3])
        : "r"(a[0]), "r"(a[1]), "r"(a[2]), "r"(a[3]), "r"(b[0]), "r"(b[1]));
}

// f32 -> (bf16 hi, bf16 lo): hi = truncate, lo = rn(x - hi). Pack pairs.
static __device__ __forceinline__ void split2(float a, float b, uint32_t& hw, uint32_t& lw) {
    uint32_t ua = __float_as_uint(a), ub = __float_as_uint(b);
    hw = (ua >> 16) | (ub & 0xFFFF0000u);          // a -> low half, b -> high half
    float la = a - __uint_as_float(ua & 0xFFFF0000u);
    float lb = b - __uint_as_float(ub & 0xFFFF0000u);
    __nv_bfloat162 t = __floats2bfloat162_rn(la, lb);
    lw = *reinterpret_cast<uint32_t*>(&t);
}

// ---------------------------------------------------------------------------
// Tensor-core GEMM (mma.sync bf16, hi/lo split):
//   C[m,n] = sum_k A[m,k] * W[n,k] + bias[n]   (M=8192, N=1024, K=1024)
// CTA tile 128x128, 8 warps (2x4), warp tile 64x32, K-chunk 32.
// MODE 0: A = g_O, write Cout       MODE 1: scatter g_Qh
// MODE 2: scatter g_Kh (quirk)      MODE 3: scatter g_Vh
// ---------------------------------------------------------------------------
constexpr int SSTR = 40;   // smem row stride in bf16 elements (80B; conflict-free)

template <int MODE>
__global__ __launch_bounds__(256, 2)
void tc_gemm(const float* __restrict__ A,
             const float* __restrict__ W,
             const float* __restrict__ bias,
             float* __restrict__ Cout)
{
    __shared__ __align__(16) uint16_t sAh[128 * SSTR];
    __shared__ __align__(16) uint16_t sAl[128 * SSTR];
    __shared__ __align__(16) uint16_t sBh[128 * SSTR];
    __shared__ __align__(16) uint16_t sBl[128 * SSTR];

    const int tid  = threadIdx.x;
    const int lane = tid & 31;
    const int wid  = tid >> 5;
    const int wm   = wid >> 2;          // 0..1
    const int wn   = wid & 3;           // 0..3
    const int bm   = blockIdx.y * 128;
    const int bn   = blockIdx.x * 128;
    const float* __restrict__ Ap = (MODE == 0) ? (const float*)g_O : A;

    const uint32_t aAh = smem_u32(sAh), aAl = smem_u32(sAl);
    const uint32_t aBh = smem_u32(sBh), aBl = smem_u32(sBl);

    // per-lane ldmatrix address components
    const int grp = lane >> 3, lr = lane & 7;
    // A tiles: t0 rows m..m+7 klo, t1 rows +8 klo, t2 rows m..m+7 khi, t3 +8 khi
    const int baseA = (wm * 64 + (grp & 1) * 8 + lr) * SSTR + (grp >> 1) * 8;
    // B tiles (x4 covers n-tile pair p): t0 (nt,klo), t1 (nt,khi), t2 (nt+1,klo), t3 (nt+1,khi)
    const int baseB = (wn * 32 + (grp >> 1) * 8 + lr) * SSTR + (grp & 1) * 8;

    float c[4][4][4];
#pragma unroll
    for (int mt = 0; mt < 4; mt++)
#pragma unroll
        for (int nt = 0; nt < 4; nt++)
#pragma unroll
            for (int q = 0; q < 4; q++) c[mt][nt][q] = 0.f;

    for (int k0 = 0; k0 < Dm; k0 += 32) {
        // ---- stage A/B chunk as bf16 hi/lo ----
#pragma unroll
        for (int i = 0; i < 2; i++) {
            const int idx = tid + i * 256;      // 0..511
            const int row = idx >> 2;           // 0..127
            const int g   = idx & 3;            // group of 8 k
            const int so  = row * SSTR + g * 8; // element offset
            {
                const float4* p = (const float4*)(Ap + (size_t)(bm + row) * Dm + k0 + g * 8);
                float4 u = p[0], v = p[1];
                uint32_t h0, h1, h2, h3, l0, l1, l2, l3;
                split2(u.x, u.y, h0, l0); split2(u.z, u.w, h1, l1);
                split2(v.x, v.y, h2, l2); split2(v.z, v.w, h3, l3);
                *(uint4*)(sAh + so) = make_uint4(h0, h1, h2, h3);
                *(uint4*)(sAl + so) = make_uint4(l0, l1, l2, l3);
            }
            {
                const float4* p = (const float4*)(W + (size_t)(bn + row) * Dm + k0 + g * 8);
                float4 u = p[0], v = p[1];
                uint32_t h0, h1, h2, h3, l0, l1, l2, l3;
                split2(u.x, u.y, h0, l0); split2(u.z, u.w, h1, l1);
                split2(v.x, v.y, h2, l2); split2(v.z, v.w, h3, l3);
                *(uint4*)(sBh + so) = make_uint4(h0, h1, h2, h3);
                *(uint4*)(sBl + so) = make_uint4(l0, l1, l2, l3);
            }
        }
        __syncthreads();

        // ---- mma over the 32-k chunk (two k16 steps) ----
#pragma unroll
        for (int ks = 0; ks < 32; ks += 16) {
            uint32_t Bh[8], Bl[8];      // [nt*2 + khalf]
#pragma unroll
            for (int p = 0; p < 2; p++) {
                const uint32_t off = (uint32_t)(baseB + p * 16 * SSTR + ks) * 2u;
                ldmx4(&Bh[p * 4], aBh + off);
                ldmx4(&Bl[p * 4], aBl + off);
            }
#pragma unroll
            for (int mt = 0; mt < 4; mt++) {
                uint32_t Ah[4], Al[4];
                const uint32_t off = (uint32_t)(baseA + mt * 16 * SSTR + ks) * 2u;
                ldmx4(Ah, aAh + off);
                ldmx4(Al, aAl + off);
#pragma unroll
                for (int nt = 0; nt < 4; nt++) {
                    mma_bf16(c[mt][nt], Ah, &Bh[nt * 2]);
                    mma_bf16(c[mt][nt], Ah, &Bl[nt * 2]);
                    mma_bf16(c[mt][nt], Al, &Bh[nt * 2]);
                }
            }
        }
        __syncthreads();
    }

    // ---- epilogue: +bias, MODE scatter ----
#pragma unroll
    for (int mt = 0; mt < 4; mt++) {
#pragma unroll
        for (int nt = 0; nt < 4; nt++) {
            const float* cc = c[mt][nt];
            const int m0 = bm + wm * 64 + mt * 16 + (lane >> 2);
            const int n0 = bn + wn * 32 + nt * 8 + 2 * (lane & 3);
            const float b0 = __ldg(&bias[n0]);
            const float b1 = __ldg(&bias[n0 + 1]);
#pragma unroll
            for (int h = 0; h < 2; h++) {
                const int m  = m0 + h * 8;
                const float v0 = cc[h * 2 + 0] + b0;
                const float v1 = cc[h * 2 + 1] + b1;
                const int bb = m >> 11;
                const int ss = m & 2047;
                if (MODE == 0) {
                    *(float2*)(Cout + (size_t)m * Dm + n0) = make_float2(v0, v1);
                } else if (MODE == 2) {
                    g_Kh[(((size_t)(bb * Hn + (n0 & 15)) * Sseq + ss) << 6) + (n0 >> 4)] = v0;
                    g_Kh[(((size_t)(bb * Hn + ((n0 + 1) & 15)) * Sseq + ss) << 6) + ((n0 + 1) >> 4)] = v1;
                } else {
                    float* dst = (MODE == 1) ? g_Qh : g_Vh;
                    *(float2*)(dst + (((size_t)(bb * Hn + (n0 >> 6)) * Sseq + ss) << 6) + (n0 & 63))
                        = make_float2(v0, v1);
                }
            }
        }
    }
}

// ---------------------------------------------------------------------------
// Flash attention, causal, fp32 (unchanged — verified, 1163us)
// ---------------------------------------------------------------------------
constexpr int QS = 68;   // smem row stride (floats)

__global__ __launch_bounds__(256, 2)
void attn_kernel()
{
    extern __shared__ float sm[];
    float* Qs = sm;                 // [64][QS], [d][r], pre-scaled
    float* Ks = Qs + 64 * QS;       // [64][QS], [d][s]
    float* Vs = Ks + 64 * QS;       // [64][QS], [s][c]
    float* Ps = Vs + 64 * QS;       // [64][QS], [s][r]

    const int qt  = blockIdx.x;
    const int bh  = blockIdx.y;
    const int tid = threadIdx.x;
    const int tx  = tid & 15;
    const int ty  = tid >> 4;
    const int r0  = ty * 4;
    const int c0  = tx * 4;

    const size_t headOff = (size_t)bh * Sseq * DHc;
    const float* __restrict__ Qb = g_Qh + headOff + (size_t)qt * 64 * DHc;
    const float scale = 0.125f;

#pragma unroll
    for (int i = 0; i < 4; i++) {
        int f  = tid + i * 256;
        int r  = f >> 4;
        int d4 = (f & 15) << 2;
        float4 q = *(const float4*)(Qb + r * DHc + d4);
        Qs[(d4 + 0) * QS + r] = q.x * scale;
        Qs[(d4 + 1) * QS + r] = q.y * scale;
        Qs[(d4 + 2) * QS + r] = q.z * scale;
        Qs[(d4 + 3) * QS + r] = q.w * scale;
    }

    float m_run[4], l_run[4], Oacc[4][4];
#pragma unroll
    for (int i = 0; i < 4; i++) {
        m_run[i] = -1e30f;
        l_run[i] = 0.f;
#pragma unroll
        for (int j = 0; j < 4; j++) Oacc[i][j] = 0.f;
    }

    for (int j = 0; j <= qt; j++) {
        __syncthreads();
        const float* __restrict__ Kb = g_Kh + headOff + (size_t)j * 64 * DHc;
        const float* __restrict__ Vb = g_Vh + headOff + (size_t)j * 64 * DHc;
#pragma unroll
        for (int i = 0; i < 4; i++) {
            int f  = tid + i * 256;
            int r  = f >> 4;
            int d4 = (f & 15) << 2;
            float4 k = *(const float4*)(Kb + r * DHc + d4);
            Ks[(d4 + 0) * QS + r] = k.x;
            Ks[(d4 + 1) * QS + r] = k.y;
            Ks[(d4 + 2) * QS + r] = k.z;
            Ks[(d4 + 3) * QS + r] = k.w;
            float4 v = *(const float4*)(Vb + r * DHc + d4);
            *(float4*)(Vs + r * QS + d4) = v;
        }
        __syncthreads();

        float sc[4][4];
#pragma unroll
        for (int i = 0; i < 4; i++)
#pragma unroll
            for (int jj = 0; jj < 4; jj++) sc[i][jj] = 0.f;

#pragma unroll 16
        for (int d = 0; d < 64; d++) {
            float4 qv = *(const float4*)(Qs + d * QS + r0);
            float4 kv = *(const float4*)(Ks + d * QS + c0);
            float qa[4] = {qv.x, qv.y, qv.z, qv.w};
            float kb[4] = {kv.x, kv.y, kv.z, kv.w};
#pragma unroll
            for (int i = 0; i < 4; i++)
#pragma unroll
                for (int jj = 0; jj < 4; jj++)
                    sc[i][jj] = fmaf(qa[i], kb[jj], sc[i][jj]);
        }

        if (j == qt) {
#pragma unroll
            for (int i = 0; i < 4; i++)
#pragma unroll
                for (int jj = 0; jj < 4; jj++)
                    if (c0 + jj > r0 + i) sc[i][jj] = -1e30f;
        }

#pragma unroll
        for (int i = 0; i < 4; i++) {
            float v = fmaxf(fmaxf(sc[i][0], sc[i][1]), fmaxf(sc[i][2], sc[i][3]));
#pragma unroll
            for (int off = 8; off >= 1; off >>= 1)
                v = fmaxf(v, __shfl_xor_sync(0xffffffffu, v, off, 16));
            const float mnew  = fmaxf(m_run[i], v);
            const float alpha = __expf(m_run[i] - mnew);
            m_run[i] = mnew;

            float p0 = __expf(sc[i][0] - mnew);
            float p1 = __expf(sc[i][1] - mnew);
            float p2 = __expf(sc[i][2] - mnew);
            float p3 = __expf(sc[i][3] - mnew);
            float rs = (p0 + p1) + (p2 + p3);
#pragma unroll
            for (int off = 8; off >= 1; off >>= 1)
                rs += __shfl_xor_sync(0xffffffffu, rs, off, 16);
            l_run[i] = l_run[i] * alpha + rs;
#pragma unroll
            for (int jj = 0; jj < 4; jj++) Oacc[i][jj] *= alpha;

            Ps[(c0 + 0) * QS + r0 + i] = p0;
            Ps[(c0 + 1) * QS + r0 + i] = p1;
            Ps[(c0 + 2) * QS + r0 + i] = p2;
            Ps[(c0 + 3) * QS + r0 + i] = p3;
        }
        __syncthreads();

#pragma unroll 16
        for (int s = 0; s < 64; s++) {
            float4 pv = *(const float4*)(Ps + s * QS + r0);
            float4 vv = *(const float4*)(Vs + s * QS + c0);
            float pa[4] = {pv.x, pv.y, pv.z, pv.w};
            float vb[4] = {vv.x, vv.y, vv.z, vv.w};
#pragma unroll
            for (int i = 0; i < 4; i++)
#pragma unroll
                for (int jj = 0; jj < 4; jj++)
                    Oacc[i][jj] = fmaf(pa[i], vb[jj], Oacc[i][jj]);
        }
    }

    const int bb = bh >> 4;
    const int hh = bh & 15;
#pragma unroll
    for (int i = 0; i < 4; i++) {
        const float inv = 1.0f / l_run[i];
        const int qrow  = qt * 64 + r0 + i;
        float4 o;
        o.x = Oacc[i][0] * inv;
        o.y = Oacc[i][1] * inv;
        o.z = Oacc[i][2] * inv;
        o.w = Oacc[i][3] * inv;
        *(float4*)(g_O + (size_t)(bb * Sseq + qrow) * Dm + hh * DHc + c0) = o;
    }
}

// ---------------------------------------------------------------------------
// Launch
// ---------------------------------------------------------------------------
extern "C" void kernel_launch(void* const* d_in, const int* in_sizes, int n_in,
                              void* d_out, int out_size)
{
    const float* x  = (const float*)d_in[0];
    const float* Wq = (const float*)d_in[1];
    const float* bq = (const float*)d_in[2];
    const float* Wk = (const float*)d_in[3];
    const float* bk = (const float*)d_in[4];
    const float* Wv = (const float*)d_in[5];
    const float* bv = (const float*)d_in[6];
    const float* Wp = (const float*)d_in[7];
    const float* bp = (const float*)d_in[8];
    float* out = (float*)d_out;

    const dim3 gg(Dm / 128, Mrows / 128);   // (8, 64)

    tc_gemm<1><<<gg, 256>>>(x, Wq, bq, nullptr);
    tc_gemm<2><<<gg, 256>>>(x, Wk, bk, nullptr);
    tc_gemm<3><<<gg, 256>>>(x, Wv, bv, nullptr);

    const int smem = 4 * 64 * QS * (int)sizeof(float);  // 69,632 B
    cudaFuncSetAttribute(attn_kernel, cudaFuncAttributeMaxDynamicSharedMemorySize, smem);
    attn_kernel<<<dim3(Sseq / 64, Bc * Hn), 256, smem>>>();

    tc_gemm<0><<<gg, 256>>>(nullptr, Wp, bp, out);
}

// round 5
// speedup vs baseline: 2.5772x; 1.6664x over previous
#include <cuda_runtime.h>
#include <cuda_bf16.h>
#include <cstdint>

// ---------------------------------------------------------------------------
// Problem constants
// ---------------------------------------------------------------------------
constexpr int Bc   = 4;
constexpr int Sseq = 2048;
constexpr int Dm   = 1024;
constexpr int Hn   = 16;
constexpr int DHc  = 64;
constexpr int Mrows = Bc * Sseq;     // 8192
constexpr size_t HSD = (size_t)Bc * Hn * Sseq * DHc;   // 8,388,608

// Device-global scratch (no cudaMalloc allowed)
__device__ __nv_bfloat16 g_qh[HSD], g_ql[HSD];   // Q hi/lo, [B,H,S,DH], scale folded
__device__ __nv_bfloat16 g_kh[HSD], g_kl[HSD];   // K hi/lo, quirk layout
__device__ __nv_bfloat16 g_vh[HSD], g_vl[HSD];   // V hi/lo
__device__ float g_O[(size_t)Mrows * Dm];        // attention output, [B*S, D]

// ---------------------------------------------------------------------------
// Helpers (baseline sm_80+ instructions only — no "a"-suffix features)
// ---------------------------------------------------------------------------
static __device__ __forceinline__ uint32_t smem_u32(const void* p) {
    uint32_t a;
    asm("{ .reg .u64 t; cvta.to.shared.u64 t, %1; cvt.u32.u64 %0, t; }"
        : "=r"(a) : "l"(p));
    return a;
}

static __device__ __forceinline__ void ldmx4(uint32_t* r, uint32_t addr) {
    asm volatile("ldmatrix.sync.aligned.m8n8.x4.shared.b16 {%0,%1,%2,%3}, [%4];"
        : "=r"(r[0]), "=r"(r[1]), "=r"(r[2]), "=r"(r[3]) : "r"(addr));
}

static __device__ __forceinline__ void ldmx4t(uint32_t* r, uint32_t addr) {
    asm volatile("ldmatrix.sync.aligned.m8n8.x4.trans.shared.b16 {%0,%1,%2,%3}, [%4];"
        : "=r"(r[0]), "=r"(r[1]), "=r"(r[2]), "=r"(r[3]) : "r"(addr));
}

static __device__ __forceinline__ void mma_bf16(float* c, const uint32_t* a, const uint32_t* b) {
    asm volatile(
        "mma.sync.aligned.m16n8k16.row.col.f32.bf16.bf16.f32 "
        "{%0,%1,%2,%3}, {%4,%5,%6,%7}, {%8,%9}, {%0,%1,%2,%3};"
        : "+f"(c[0]), "+f"(c[1]), "+f"(c[2]), "+f"(c[3])
        : "r"(a[0]), "r"(a[1]), "r"(a[2]), "r"(a[3]), "r"(b[0]), "r"(b[1]));
}

// f32 -> (bf16 hi, bf16 lo): hi = truncate, lo = rn(x - hi). Pack pairs (a=low half).
static __device__ __forceinline__ void split2(float a, float b, uint32_t& hw, uint32_t& lw) {
    uint32_t ua = __float_as_uint(a), ub = __float_as_uint(b);
    hw = (ua >> 16) | (ub & 0xFFFF0000u);
    float la = a - __uint_as_float(ua & 0xFFFF0000u);
    float lb = b - __uint_as_float(ub & 0xFFFF0000u);
    __nv_bfloat162 t = __floats2bfloat162_rn(la, lb);
    lw = *reinterpret_cast<uint32_t*>(&t);
}

static __device__ __forceinline__ void split1(float v, __nv_bfloat16& h, __nv_bfloat16& l) {
    uint32_t u = __float_as_uint(v) & 0xFFFF0000u;
    h = *reinterpret_cast<__nv_bfloat16*>(reinterpret_cast<uint16_t*>(&u) + 1);
    uint16_t hb = (uint16_t)(__float_as_uint(v) >> 16);
    h = *reinterpret_cast<__nv_bfloat16*>(&hb);
    l = __float2bfloat16(v - __uint_as_float(u));
}

// ---------------------------------------------------------------------------
// Tensor-core projection GEMM (mma.sync bf16, hi/lo split):
//   C[m,n] = sum_k A[m,k] * W[n,k] + bias[n]   (M=8192, N=1024, K=1024)
// CTA tile 128x128, 8 warps (2x4), warp tile 64x32, K-chunk 32.
// MODE 0: A = g_O, write f32 Cout        MODE 1: split-scatter g_qh/g_ql (x1/8)
// MODE 2: split-scatter g_kh/g_kl quirk  MODE 3: split-scatter g_vh/g_vl
// ---------------------------------------------------------------------------
constexpr int SSTR = 40;   // smem row stride in bf16 elements

template <int MODE>
__global__ __launch_bounds__(256, 2)
void tc_gemm(const float* __restrict__ A,
             const float* __restrict__ W,
             const float* __restrict__ bias,
             float* __restrict__ Cout)
{
    __shared__ __align__(16) uint16_t sAh[128 * SSTR];
    __shared__ __align__(16) uint16_t sAl[128 * SSTR];
    __shared__ __align__(16) uint16_t sBh[128 * SSTR];
    __shared__ __align__(16) uint16_t sBl[128 * SSTR];

    const int tid  = threadIdx.x;
    const int lane = tid & 31;
    const int wid  = tid >> 5;
    const int wm   = wid >> 2;
    const int wn   = wid & 3;
    const int bm   = blockIdx.y * 128;
    const int bn   = blockIdx.x * 128;
    const float* __restrict__ Ap = (MODE == 0) ? (const float*)g_O : A;

    const uint32_t aAh = smem_u32(sAh), aAl = smem_u32(sAl);
    const uint32_t aBh = smem_u32(sBh), aBl = smem_u32(sBl);

    const int grp = lane >> 3, lr = lane & 7;
    const int baseA = (wm * 64 + (grp & 1) * 8 + lr) * SSTR + (grp >> 1) * 8;
    const int baseB = (wn * 32 + (grp >> 1) * 8 + lr) * SSTR + (grp & 1) * 8;

    float c[4][4][4];
#pragma unroll
    for (int mt = 0; mt < 4; mt++)
#pragma unroll
        for (int nt = 0; nt < 4; nt++)
#pragma unroll
            for (int q = 0; q < 4; q++) c[mt][nt][q] = 0.f;

    for (int k0 = 0; k0 < Dm; k0 += 32) {
#pragma unroll
        for (int i = 0; i < 2; i++) {
            const int idx = tid + i * 256;
            const int row = idx >> 2;
            const int g   = idx & 3;
            const int so  = row * SSTR + g * 8;
            {
                const float4* p = (const float4*)(Ap + (size_t)(bm + row) * Dm + k0 + g * 8);
                float4 u = p[0], v = p[1];
                uint32_t h0, h1, h2, h3, l0, l1, l2, l3;
                split2(u.x, u.y, h0, l0); split2(u.z, u.w, h1, l1);
                split2(v.x, v.y, h2, l2); split2(v.z, v.w, h3, l3);
                *(uint4*)(sAh + so) = make_uint4(h0, h1, h2, h3);
                *(uint4*)(sAl + so) = make_uint4(l0, l1, l2, l3);
            }
            {
                const float4* p = (const float4*)(W + (size_t)(bn + row) * Dm + k0 + g * 8);
                float4 u = p[0], v = p[1];
                uint32_t h0, h1, h2, h3, l0, l1, l2, l3;
                split2(u.x, u.y, h0, l0); split2(u.z, u.w, h1, l1);
                split2(v.x, v.y, h2, l2); split2(v.z, v.w, h3, l3);
                *(uint4*)(sBh + so) = make_uint4(h0, h1, h2, h3);
                *(uint4*)(sBl + so) = make_uint4(l0, l1, l2, l3);
            }
        }
        __syncthreads();

#pragma unroll
        for (int ks = 0; ks < 32; ks += 16) {
            uint32_t Bh[8], Bl[8];
#pragma unroll
            for (int p = 0; p < 2; p++) {
                const uint32_t off = (uint32_t)(baseB + p * 16 * SSTR + ks) * 2u;
                ldmx4(&Bh[p * 4], aBh + off);
                ldmx4(&Bl[p * 4], aBl + off);
            }
#pragma unroll
            for (int mt = 0; mt < 4; mt++) {
                uint32_t Ah[4], Al[4];
                const uint32_t off = (uint32_t)(baseA + mt * 16 * SSTR + ks) * 2u;
                ldmx4(Ah, aAh + off);
                ldmx4(Al, aAl + off);
#pragma unroll
                for (int nt = 0; nt < 4; nt++) {
                    mma_bf16(c[mt][nt], Ah, &Bh[nt * 2]);
                    mma_bf16(c[mt][nt], Ah, &Bl[nt * 2]);
                    mma_bf16(c[mt][nt], Al, &Bh[nt * 2]);
                }
            }
        }
        __syncthreads();
    }

    // ---- epilogue ----
#pragma unroll
    for (int mt = 0; mt < 4; mt++) {
#pragma unroll
        for (int nt = 0; nt < 4; nt++) {
            const float* cc = c[mt][nt];
            const int m0 = bm + wm * 64 + mt * 16 + (lane >> 2);
            const int n0 = bn + wn * 32 + nt * 8 + 2 * (lane & 3);
            const float b0 = __ldg(&bias[n0]);
            const float b1 = __ldg(&bias[n0 + 1]);
#pragma unroll
            for (int h = 0; h < 2; h++) {
                const int m  = m0 + h * 8;
                float v0 = cc[h * 2 + 0] + b0;
                float v1 = cc[h * 2 + 1] + b1;
                const int bb = m >> 11;
                const int ss = m & 2047;
                if (MODE == 0) {
                    *(float2*)(Cout + (size_t)m * Dm + n0) = make_float2(v0, v1);
                } else if (MODE == 2) {
                    __nv_bfloat16 h0, l0, h1, l1;
                    split1(v0, h0, l0); split1(v1, h1, l1);
                    const size_t i0 = (((size_t)(bb * Hn + (n0 & 15)) * Sseq + ss) << 6) + (n0 >> 4);
                    const size_t i1 = (((size_t)(bb * Hn + ((n0 + 1) & 15)) * Sseq + ss) << 6) + ((n0 + 1) >> 4);
                    g_kh[i0] = h0; g_kl[i0] = l0;
                    g_kh[i1] = h1; g_kl[i1] = l1;
                } else {
                    if (MODE == 1) { v0 *= 0.125f; v1 *= 0.125f; }   // fold softmax scale
                    uint32_t hw, lw;
                    split2(v0, v1, hw, lw);
                    const size_t idx = (((size_t)(bb * Hn + (n0 >> 6)) * Sseq + ss) << 6) + (n0 & 63);
                    __nv_bfloat16* dh = (MODE == 1) ? g_qh : g_vh;
                    __nv_bfloat16* dl = (MODE == 1) ? g_ql : g_vl;
                    *(uint32_t*)(dh + idx) = hw;
                    *(uint32_t*)(dl + idx) = lw;
                }
            }
        }
    }
}

// ---------------------------------------------------------------------------
// Flash attention via mma.sync bf16 hi/lo. Block = 256 thr / 8 warps.
// q-tile 128 (warp owns 16 rows), kv-tile 64, one (b,h) per blockIdx.y.
// ---------------------------------------------------------------------------
constexpr int VSTR = 72;   // smem row stride (bf16 elems); 144B rows, LDSM conflict-free

__global__ __launch_bounds__(256, 2)
void attn_mma()
{
    __shared__ __align__(16) uint16_t sbuf[4 * 64 * VSTR];   // 36,864 B
    // region element offsets (phase 2): Kh=0, Kl=4608, Vh=9216, Vl=13824
    const int tid  = threadIdx.x;
    const int lane = tid & 31;
    const int w    = tid >> 5;
    const int qt   = (int)gridDim.x - 1 - (int)blockIdx.x;   // heavy blocks first
    const int bh   = blockIdx.y;
    const int grp  = lane >> 3, lr = lane & 7;
    const uint32_t sb = smem_u32(sbuf);

    // ---- stage Q hi/lo (rows 0..127), load A-fragments, release smem ----
    const size_t qbase = ((size_t)bh * Sseq + (size_t)qt * 128) * 64;
#pragma unroll
    for (int i = 0; i < 4; i++) {
        const int idx = tid + i * 256;      // 0..1023
        const int row = idx >> 3;
        const int c8  = (idx & 7) * 8;
        *(uint4*)&sbuf[row * VSTR + c8]        = *(const uint4*)((const uint16_t*)g_qh + qbase + row * 64 + c8);
        *(uint4*)&sbuf[9216 + row * VSTR + c8] = *(const uint4*)((const uint16_t*)g_ql + qbase + row * 64 + c8);
    }
    __syncthreads();
    uint32_t Qh[4][4], Ql[4][4];
#pragma unroll
    for (int ks = 0; ks < 4; ks++) {
        const int off = (w * 16 + (grp & 1) * 8 + lr) * VSTR + ks * 16 + (grp >> 1) * 8;
        ldmx4(Qh[ks], sb + (uint32_t)off * 2u);
        ldmx4(Ql[ks], sb + (uint32_t)(off + 9216) * 2u);
    }

    float O[8][4];
#pragma unroll
    for (int nt = 0; nt < 8; nt++)
#pragma unroll
        for (int q = 0; q < 4; q++) O[nt][q] = 0.f;
    float m_lo = -1e30f, m_hi = -1e30f, l_lo = 0.f, l_hi = 0.f;

    const int row_lo_g = qt * 128 + w * 16 + (lane >> 2);   // global q row (lo half)
    const size_t kvb0 = (size_t)bh * Sseq * 64;
    const int jmax = 2 * qt + 1;

    for (int j = 0; j <= jmax; j++) {
        __syncthreads();
        const size_t kb = kvb0 + (size_t)j * 64 * 64;
#pragma unroll
        for (int i = 0; i < 2; i++) {
            const int idx = tid + i * 256;      // 0..511
            const int row = idx >> 3;
            const int c8  = (idx & 7) * 8;
            const int so  = row * VSTR + c8;
            const size_t go = kb + row * 64 + c8;
            *(uint4*)&sbuf[so]         = *(const uint4*)((const uint16_t*)g_kh + go);
            *(uint4*)&sbuf[4608 + so]  = *(const uint4*)((const uint16_t*)g_kl + go);
            *(uint4*)&sbuf[9216 + so]  = *(const uint4*)((const uint16_t*)g_vh + go);
            *(uint4*)&sbuf[13824 + so] = *(const uint4*)((const uint16_t*)g_vl + go);
        }
        __syncthreads();

        // ---- S = Q @ K^T (hi/lo 3-term) ----
        float S[8][4];
#pragma unroll
        for (int nt = 0; nt < 8; nt++)
#pragma unroll
            for (int q = 0; q < 4; q++) S[nt][q] = 0.f;

#pragma unroll
        for (int ks = 0; ks < 4; ks++) {
#pragma unroll
            for (int np = 0; np < 4; np++) {
                uint32_t KBh[4], KBl[4];
                const int off = (np * 16 + (grp >> 1) * 8 + lr) * VSTR + ks * 16 + (grp & 1) * 8;
                ldmx4(KBh, sb + (uint32_t)off * 2u);
                ldmx4(KBl, sb + (uint32_t)(off + 4608) * 2u);
                mma_bf16(S[np * 2], Qh[ks], KBh);
                mma_bf16(S[np * 2], Qh[ks], KBl);
                mma_bf16(S[np * 2], Ql[ks], KBh);
                mma_bf16(S[np * 2 + 1], Qh[ks], KBh + 2);
                mma_bf16(S[np * 2 + 1], Qh[ks], KBl + 2);
                mma_bf16(S[np * 2 + 1], Ql[ks], KBh + 2);
            }
        }

        // ---- causal mask (only needed on last two kv tiles) ----
        if (j >= 2 * qt) {
#pragma unroll
            for (int nt = 0; nt < 8; nt++)
#pragma unroll
                for (int q = 0; q < 4; q++) {
                    const int col = j * 64 + nt * 8 + 2 * (lane & 3) + (q & 1);
                    const int row = row_lo_g + (q >> 1) * 8;
                    if (col > row) S[nt][q] = -1e30f;
                }
        }

        // ---- online softmax ----
        float vlo = -1e30f, vhi = -1e30f;
#pragma unroll
        for (int nt = 0; nt < 8; nt++) {
            vlo = fmaxf(vlo, fmaxf(S[nt][0], S[nt][1]));
            vhi = fmaxf(vhi, fmaxf(S[nt][2], S[nt][3]));
        }
        vlo = fmaxf(vlo, __shfl_xor_sync(0xffffffffu, vlo, 1));
        vlo = fmaxf(vlo, __shfl_xor_sync(0xffffffffu, vlo, 2));
        vhi = fmaxf(vhi, __shfl_xor_sync(0xffffffffu, vhi, 1));
        vhi = fmaxf(vhi, __shfl_xor_sync(0xffffffffu, vhi, 2));

        const float mn_lo = fmaxf(m_lo, vlo);
        const float mn_hi = fmaxf(m_hi, vhi);
        const float al = __expf(m_lo - mn_lo);
        const float ah = __expf(m_hi - mn_hi);
        m_lo = mn_lo; m_hi = mn_hi;

        float slo = 0.f, shi = 0.f;
#pragma unroll
        for (int nt = 0; nt < 8; nt++) {
            S[nt][0] = __expf(S[nt][0] - mn_lo);
            S[nt][1] = __expf(S[nt][1] - mn_lo);
            S[nt][2] = __expf(S[nt][2] - mn_hi);
            S[nt][3] = __expf(S[nt][3] - mn_hi);
            slo += S[nt][0] + S[nt][1];
            shi += S[nt][2] + S[nt][3];
        }
        slo += __shfl_xor_sync(0xffffffffu, slo, 1);
        slo += __shfl_xor_sync(0xffffffffu, slo, 2);
        shi += __shfl_xor_sync(0xffffffffu, shi, 1);
        shi += __shfl_xor_sync(0xffffffffu, shi, 2);
        l_lo = l_lo * al + slo;
        l_hi = l_hi * ah + shi;
#pragma unroll
        for (int nt = 0; nt < 8; nt++) {
            O[nt][0] *= al; O[nt][1] *= al;
            O[nt][2] *= ah; O[nt][3] *= ah;
        }

        // ---- O += P @ V (P from registers, V via ldmatrix.trans) ----
#pragma unroll
        for (int ks = 0; ks < 4; ks++) {
            uint32_t Ph[4], Pl[4];
            split2(S[2 * ks][0], S[2 * ks][1], Ph[0], Pl[0]);
            split2(S[2 * ks][2], S[2 * ks][3], Ph[1], Pl[1]);
            split2(S[2 * ks + 1][0], S[2 * ks + 1][1], Ph[2], Pl[2]);
            split2(S[2 * ks + 1][2], S[2 * ks + 1][3], Ph[3], Pl[3]);
#pragma unroll
            for (int np = 0; np < 4; np++) {
                uint32_t VBh[4], VBl[4];
                const int off = (ks * 16 + (grp & 1) * 8 + lr) * VSTR + np * 16 + (grp >> 1) * 8;
                ldmx4t(VBh, sb + (uint32_t)(9216 + off) * 2u);
                ldmx4t(VBl, sb + (uint32_t)(13824 + off) * 2u);
                mma_bf16(O[np * 2], Ph, VBh);
                mma_bf16(O[np * 2], Ph, VBl);
                mma_bf16(O[np * 2], Pl, VBh);
                mma_bf16(O[np * 2 + 1], Ph, VBh + 2);
                mma_bf16(O[np * 2 + 1], Ph, VBl + 2);
                mma_bf16(O[np * 2 + 1], Pl, VBh + 2);
            }
        }
    }

    // ---- epilogue: normalize, write [B,S,D] ----
    const float inv_lo = 1.0f / l_lo;
    const float inv_hi = 1.0f / l_hi;
    const int bb = bh >> 4, hh = bh & 15;
    const int col0 = hh * 64 + 2 * (lane & 3);
#pragma unroll
    for (int nt = 0; nt < 8; nt++) {
        const int col = col0 + nt * 8;
        *(float2*)(g_O + ((size_t)bb * Sseq + row_lo_g) * Dm + col)
            = make_float2(O[nt][0] * inv_lo, O[nt][1] * inv_lo);
        *(float2*)(g_O + ((size_t)bb * Sseq + row_lo_g + 8) * Dm + col)
            = make_float2(O[nt][2] * inv_hi, O[nt][3] * inv_hi);
    }
}

// ---------------------------------------------------------------------------
// Launch
// ---------------------------------------------------------------------------
extern "C" void kernel_launch(void* const* d_in, const int* in_sizes, int n_in,
                              void* d_out, int out_size)
{
    const float* x  = (const float*)d_in[0];
    const float* Wq = (const float*)d_in[1];
    const float* bq = (const float*)d_in[2];
    const float* Wk = (const float*)d_in[3];
    const float* bk = (const float*)d_in[4];
    const float* Wv = (const float*)d_in[5];
    const float* bv = (const float*)d_in[6];
    const float* Wp = (const float*)d_in[7];
    const float* bp = (const float*)d_in[8];
    float* out = (float*)d_out;

    const dim3 gg(Dm / 128, Mrows / 128);   // (8, 64)

    tc_gemm<1><<<gg, 256>>>(x, Wq, bq, nullptr);
    tc_gemm<2><<<gg, 256>>>(x, Wk, bk, nullptr);
    tc_gemm<3><<<gg, 256>>>(x, Wv, bv, nullptr);

    attn_mma<<<dim3(Sseq / 128, Bc * Hn), 256>>>();

    tc_gemm<0><<<gg, 256>>>(nullptr, Wp, bp, out);
}

// round 12
// speedup vs baseline: 2.5940x; 1.0065x over previous
#include <cuda_runtime.h>
#include <cuda_bf16.h>
#include <cstdint>

// ---------------------------------------------------------------------------
// Problem constants
// ---------------------------------------------------------------------------
constexpr int Bc   = 4;
constexpr int Sseq = 2048;
constexpr int Dm   = 1024;
constexpr int Hn   = 16;
constexpr int DHc  = 64;
constexpr int Mrows = Bc * Sseq;     // 8192
constexpr size_t HSD = (size_t)Bc * Hn * Sseq * DHc;   // 8,388,608
constexpr size_t XSZ = (size_t)Mrows * Dm;             // 8,388,608
constexpr size_t WSZ = (size_t)Dm * Dm;                // 1,048,576

// Device-global scratch (no cudaMalloc allowed); 16B-aligned for uint4 access
__device__ __align__(16) __nv_bfloat16 g_qh[HSD], g_ql[HSD];   // Q hi/lo, scale folded
__device__ __align__(16) __nv_bfloat16 g_kh[HSD], g_kl[HSD];   // K hi/lo, quirk layout
__device__ __align__(16) __nv_bfloat16 g_vh[HSD], g_vl[HSD];   // V hi/lo
__device__ __align__(16) __nv_bfloat16 g_xh[XSZ], g_xl[XSZ];   // input x hi/lo
__device__ __align__(16) __nv_bfloat16 g_oh[XSZ], g_ol[XSZ];   // attention out hi/lo
__device__ __align__(16) __nv_bfloat16 g_wqh[WSZ], g_wql[WSZ];
__device__ __align__(16) __nv_bfloat16 g_wkh[WSZ], g_wkl[WSZ];
__device__ __align__(16) __nv_bfloat16 g_wvh[WSZ], g_wvl[WSZ];
__device__ __align__(16) __nv_bfloat16 g_wph[WSZ], g_wpl[WSZ];

// ---------------------------------------------------------------------------
// Helpers (baseline sm_80+ only)
// ---------------------------------------------------------------------------
static __device__ __forceinline__ uint32_t smem_u32(const void* p) {
    uint32_t a;
    asm("{ .reg .u64 t; cvta.to.shared.u64 t, %1; cvt.u32.u64 %0, t; }"
        : "=r"(a) : "l"(p));
    return a;
}

static __device__ __forceinline__ void ldmx4(uint32_t* r, uint32_t addr) {
    asm volatile("ldmatrix.sync.aligned.m8n8.x4.shared.b16 {%0,%1,%2,%3}, [%4];"
        : "=r"(r[0]), "=r"(r[1]), "=r"(r[2]), "=r"(r[3]) : "r"(addr));
}

static __device__ __forceinline__ void ldmx4t(uint32_t* r, uint32_t addr) {
    asm volatile("ldmatrix.sync.aligned.m8n8.x4.trans.shared.b16 {%0,%1,%2,%3}, [%4];"
        : "=r"(r[0]), "=r"(r[1]), "=r"(r[2]), "=r"(r[3]) : "r"(addr));
}

static __device__ __forceinline__ void mma_bf16(float* c, const uint32_t* a, const uint32_t* b) {
    asm volatile(
        "mma.sync.aligned.m16n8k16.row.col.f32.bf16.bf16.f32 "
        "{%0,%1,%2,%3}, {%4,%5,%6,%7}, {%8,%9}, {%0,%1,%2,%3};"
        : "+f"(c[0]), "+f"(c[1]), "+f"(c[2]), "+f"(c[3])
        : "r"(a[0]), "r"(a[1]), "r"(a[2]), "r"(a[3]), "r"(b[0]), "r"(b[1]));
}

// f32 -> (bf16 hi, bf16 lo): hi = truncate, lo = rn(x - hi). Pack pairs (a=low half).
static __device__ __forceinline__ void split2(float a, float b, uint32_t& hw, uint32_t& lw) {
    uint32_t ua = __float_as_uint(a), ub = __float_as_uint(b);
    hw = (ua >> 16) | (ub & 0xFFFF0000u);
    float la = a - __uint_as_float(ua & 0xFFFF0000u);
    float lb = b - __uint_as_float(ub & 0xFFFF0000u);
    __nv_bfloat162 t = __floats2bfloat162_rn(la, lb);
    lw = *reinterpret_cast<uint32_t*>(&t);
}

static __device__ __forceinline__ void split1(float v, __nv_bfloat16& h, __nv_bfloat16& l) {
    uint32_t u = __float_as_uint(v) & 0xFFFF0000u;
    uint16_t hb = (uint16_t)(__float_as_uint(v) >> 16);
    h = *reinterpret_cast<__nv_bfloat16*>(&hb);
    l = __float2bfloat16(v - __uint_as_float(u));
}

// ---------------------------------------------------------------------------
// One-shot f32 -> bf16 hi/lo converter (8 floats / thread).
// Destination globals selected IN DEVICE CODE (device symbols must never be
// passed as kernel arguments from host — that was the round-6/10 bug).
// MODE: 0=x, 1=Wq, 2=Wk, 3=Wv, 4=Wp
// ---------------------------------------------------------------------------
template <int MODE>
__global__ __launch_bounds__(256)
void split_kernel(const float* __restrict__ src)
{
    __nv_bfloat16* dh;
    __nv_bfloat16* dl;
    if (MODE == 0)      { dh = g_xh;  dl = g_xl;  }
    else if (MODE == 1) { dh = g_wqh; dl = g_wql; }
    else if (MODE == 2) { dh = g_wkh; dl = g_wkl; }
    else if (MODE == 3) { dh = g_wvh; dl = g_wvl; }
    else                { dh = g_wph; dl = g_wpl; }

    const size_t i = (size_t)blockIdx.x * 256 + threadIdx.x;
    const float4* p = (const float4*)src + 2 * i;
    float4 u = p[0], v = p[1];
    uint32_t h0, h1, h2, h3, l0, l1, l2, l3;
    split2(u.x, u.y, h0, l0); split2(u.z, u.w, h1, l1);
    split2(v.x, v.y, h2, l2); split2(v.z, v.w, h3, l3);
    ((uint4*)dh)[i] = make_uint4(h0, h1, h2, h3);
    ((uint4*)dl)[i] = make_uint4(l0, l1, l2, l3);
}

// ---------------------------------------------------------------------------
// Core GEMM body (proven round-5 synchronous staging, pre-split bf16 inputs)
// CTA tile 128x128, 8 warps (2x4), warp tile 64x32, K-chunk 32.
// ---------------------------------------------------------------------------
constexpr int SSTR = 40;   // smem row stride in bf16 elems (80B, LDSM-clean)

struct GemmCtx {
    uint32_t aAh, aAl, aBh, aBl;
    int baseA, baseB;
};

static __device__ __forceinline__ void gemm_mainloop(
    float c4[4][4][4],
    const uint16_t* __restrict__ srcA_h, const uint16_t* __restrict__ srcA_l,
    const uint16_t* __restrict__ srcB_h, const uint16_t* __restrict__ srcB_l,
    uint16_t* sAh, uint16_t* sAl, uint16_t* sBh, uint16_t* sBl,
    int bm, int bn, int tid, const GemmCtx& cx)
{
    const uint16_t* const srcs[4] = {srcA_h, srcA_l, srcB_h, srcB_l};
    uint16_t* const dsts[4] = {sAh, sAl, sBh, sBl};

    for (int c = 0; c < 32; c++) {
#pragma unroll
        for (int t = 0; t < 8; t++) {
            const int idx  = tid + t * 256;       // 0..2047
            const int tile = idx >> 9;            // 0..3
            const int r    = (idx >> 2) & 127;
            const int g    = idx & 3;
            const int rowg = (tile < 2 ? bm : bn) + r;
            *(uint4*)&dsts[tile][r * SSTR + g * 8] =
                *(const uint4*)(srcs[tile] + (size_t)rowg * Dm + c * 32 + g * 8);
        }
        __syncthreads();

#pragma unroll
        for (int ks = 0; ks < 32; ks += 16) {
            uint32_t Bh[8], Bl[8];
#pragma unroll
            for (int p = 0; p < 2; p++) {
                const uint32_t off = (uint32_t)(cx.baseB + p * 16 * SSTR + ks) * 2u;
                ldmx4(&Bh[p * 4], cx.aBh + off);
                ldmx4(&Bl[p * 4], cx.aBl + off);
            }
#pragma unroll
            for (int mt = 0; mt < 4; mt++) {
                uint32_t Ahf[4], Alf[4];
                const uint32_t off = (uint32_t)(cx.baseA + mt * 16 * SSTR + ks) * 2u;
                ldmx4(Ahf, cx.aAh + off);
                ldmx4(Alf, cx.aAl + off);
#pragma unroll
                for (int nt = 0; nt < 4; nt++) {
                    mma_bf16(c4[mt][nt], Ahf, &Bh[nt * 2]);
                    mma_bf16(c4[mt][nt], Ahf, &Bl[nt * 2]);
                    mma_bf16(c4[mt][nt], Alf, &Bh[nt * 2]);
                }
            }
        }
        __syncthreads();
    }
}

// ---------------------------------------------------------------------------
// Fused QKV projection: gridDim.z selects {Q, K, V}
// ---------------------------------------------------------------------------
__global__ __launch_bounds__(256, 2)
void qkv_gemm(const float* __restrict__ bq, const float* __restrict__ bk,
              const float* __restrict__ bv)
{
    __shared__ __align__(16) uint16_t sAh[128 * SSTR];
    __shared__ __align__(16) uint16_t sAl[128 * SSTR];
    __shared__ __align__(16) uint16_t sBh[128 * SSTR];
    __shared__ __align__(16) uint16_t sBl[128 * SSTR];

    const int tid  = threadIdx.x;
    const int lane = tid & 31;
    const int wid  = tid >> 5;
    const int wm   = wid >> 2;
    const int wn   = wid & 3;
    const int bm   = blockIdx.y * 128;
    const int bn   = blockIdx.x * 128;
    const int z    = blockIdx.z;        // 0=Q, 1=K, 2=V

    const __nv_bfloat16 *wh, *wl;
    const float* bias;
    if (z == 0)      { wh = g_wqh; wl = g_wql; bias = bq; }
    else if (z == 1) { wh = g_wkh; wl = g_wkl; bias = bk; }
    else             { wh = g_wvh; wl = g_wvl; bias = bv; }

    const int grp = lane >> 3, lr = lane & 7;
    GemmCtx cx;
    cx.aAh = smem_u32(sAh); cx.aAl = smem_u32(sAl);
    cx.aBh = smem_u32(sBh); cx.aBl = smem_u32(sBl);
    cx.baseA = (wm * 64 + (grp & 1) * 8 + lr) * SSTR + (grp >> 1) * 8;
    cx.baseB = (wn * 32 + (grp >> 1) * 8 + lr) * SSTR + (grp & 1) * 8;

    float c4[4][4][4];
#pragma unroll
    for (int mt = 0; mt < 4; mt++)
#pragma unroll
        for (int nt = 0; nt < 4; nt++)
#pragma unroll
            for (int q = 0; q < 4; q++) c4[mt][nt][q] = 0.f;

    gemm_mainloop(c4, (const uint16_t*)g_xh, (const uint16_t*)g_xl,
                  (const uint16_t*)wh, (const uint16_t*)wl,
                  sAh, sAl, sBh, sBl, bm, bn, tid, cx);

    // ---- epilogue: +bias, per-z scatter ----
#pragma unroll
    for (int mt = 0; mt < 4; mt++) {
#pragma unroll
        for (int nt = 0; nt < 4; nt++) {
            const float* cc = c4[mt][nt];
            const int m0 = bm + wm * 64 + mt * 16 + (lane >> 2);
            const int n0 = bn + wn * 32 + nt * 8 + 2 * (lane & 3);
            const float b0 = __ldg(&bias[n0]);
            const float b1 = __ldg(&bias[n0 + 1]);
#pragma unroll
            for (int h = 0; h < 2; h++) {
                const int m  = m0 + h * 8;
                float v0 = cc[h * 2 + 0] + b0;
                float v1 = cc[h * 2 + 1] + b1;
                const int bb = m >> 11;
                const int ss = m & 2047;
                if (z == 1) {   // K quirk: h = n%16, d = n/16
                    __nv_bfloat16 h0, l0, h1, l1;
                    split1(v0, h0, l0); split1(v1, h1, l1);
                    const size_t i0 = (((size_t)(bb * Hn + (n0 & 15)) * Sseq + ss) << 6) + (n0 >> 4);
                    const size_t i1 = (((size_t)(bb * Hn + ((n0 + 1) & 15)) * Sseq + ss) << 6) + ((n0 + 1) >> 4);
                    g_kh[i0] = h0; g_kl[i0] = l0;
                    g_kh[i1] = h1; g_kl[i1] = l1;
                } else {
                    if (z == 0) { v0 *= 0.125f; v1 *= 0.125f; }   // fold softmax scale
                    uint32_t hw, lw;
                    split2(v0, v1, hw, lw);
                    const size_t idx = (((size_t)(bb * Hn + (n0 >> 6)) * Sseq + ss) << 6) + (n0 & 63);
                    __nv_bfloat16* dh = (z == 0) ? g_qh : g_vh;
                    __nv_bfloat16* dl = (z == 0) ? g_ql : g_vl;
                    *(uint32_t*)(dh + idx) = hw;
                    *(uint32_t*)(dl + idx) = lw;
                }
            }
        }
    }
}

// ---------------------------------------------------------------------------
// Final projection: out = O @ Wp^T + bp  (f32 output)
// ---------------------------------------------------------------------------
__global__ __launch_bounds__(256, 2)
void out_gemm(const float* __restrict__ bias, float* __restrict__ Cout)
{
    __shared__ __align__(16) uint16_t sAh[128 * SSTR];
    __shared__ __align__(16) uint16_t sAl[128 * SSTR];
    __shared__ __align__(16) uint16_t sBh[128 * SSTR];
    __shared__ __align__(16) uint16_t sBl[128 * SSTR];

    const int tid  = threadIdx.x;
    const int lane = tid & 31;
    const int wid  = tid >> 5;
    const int wm   = wid >> 2;
    const int wn   = wid & 3;
    const int bm   = blockIdx.y * 128;
    const int bn   = blockIdx.x * 128;

    const int grp = lane >> 3, lr = lane & 7;
    GemmCtx cx;
    cx.aAh = smem_u32(sAh); cx.aAl = smem_u32(sAl);
    cx.aBh = smem_u32(sBh); cx.aBl = smem_u32(sBl);
    cx.baseA = (wm * 64 + (grp & 1) * 8 + lr) * SSTR + (grp >> 1) * 8;
    cx.baseB = (wn * 32 + (grp >> 1) * 8 + lr) * SSTR + (grp & 1) * 8;

    float c4[4][4][4];
#pragma unroll
    for (int mt = 0; mt < 4; mt++)
#pragma unroll
        for (int nt = 0; nt < 4; nt++)
#pragma unroll
            for (int q = 0; q < 4; q++) c4[mt][nt][q] = 0.f;

    gemm_mainloop(c4, (const uint16_t*)g_oh, (const uint16_t*)g_ol,
                  (const uint16_t*)g_wph, (const uint16_t*)g_wpl,
                  sAh, sAl, sBh, sBl, bm, bn, tid, cx);

#pragma unroll
    for (int mt = 0; mt < 4; mt++) {
#pragma unroll
        for (int nt = 0; nt < 4; nt++) {
            const float* cc = c4[mt][nt];
            const int m0 = bm + wm * 64 + mt * 16 + (lane >> 2);
            const int n0 = bn + wn * 32 + nt * 8 + 2 * (lane & 3);
            const float b0 = __ldg(&bias[n0]);
            const float b1 = __ldg(&bias[n0 + 1]);
#pragma unroll
            for (int h = 0; h < 2; h++) {
                const int m = m0 + h * 8;
                *(float2*)(Cout + (size_t)m * Dm + n0) =
                    make_float2(cc[h * 2 + 0] + b0, cc[h * 2 + 1] + b1);
            }
        }
    }
}

// ---------------------------------------------------------------------------
// Flash attention via mma.sync bf16 hi/lo (proven round-5 core).
// Block = 256 thr / 8 warps; q-tile 128, kv-tile 64; one (b,h) per blockIdx.y.
// Epilogue writes bf16 hi/lo output (consumed by out_gemm).
// ---------------------------------------------------------------------------
constexpr int VSTR = 72;

__global__ __launch_bounds__(256, 2)
void attn_mma()
{
    __shared__ __align__(16) uint16_t sbuf[4 * 64 * VSTR];   // 36,864 B
    const int tid  = threadIdx.x;
    const int lane = tid & 31;
    const int w    = tid >> 5;
    const int qt   = (int)gridDim.x - 1 - (int)blockIdx.x;
    const int bh   = blockIdx.y;
    const int grp  = lane >> 3, lr = lane & 7;
    const uint32_t sb = smem_u32(sbuf);

    const size_t qbase = ((size_t)bh * Sseq + (size_t)qt * 128) * 64;
#pragma unroll
    for (int i = 0; i < 4; i++) {
        const int idx = tid + i * 256;
        const int row = idx >> 3;
        const int c8  = (idx & 7) * 8;
        *(uint4*)&sbuf[row * VSTR + c8]        = *(const uint4*)((const uint16_t*)g_qh + qbase + row * 64 + c8);
        *(uint4*)&sbuf[9216 + row * VSTR + c8] = *(const uint4*)((const uint16_t*)g_ql + qbase + row * 64 + c8);
    }
    __syncthreads();
    uint32_t Qh[4][4], Ql[4][4];
#pragma unroll
    for (int ks = 0; ks < 4; ks++) {
        const int off = (w * 16 + (grp & 1) * 8 + lr) * VSTR + ks * 16 + (grp >> 1) * 8;
        ldmx4(Qh[ks], sb + (uint32_t)off * 2u);
        ldmx4(Ql[ks], sb + (uint32_t)(off + 9216) * 2u);
    }

    float O[8][4];
#pragma unroll
    for (int nt = 0; nt < 8; nt++)
#pragma unroll
        for (int q = 0; q < 4; q++) O[nt][q] = 0.f;
    float m_lo = -1e30f, m_hi = -1e30f, l_lo = 0.f, l_hi = 0.f;

    const int row_lo_g = qt * 128 + w * 16 + (lane >> 2);
    const size_t kvb0 = (size_t)bh * Sseq * 64;
    const int jmax = 2 * qt + 1;

    for (int j = 0; j <= jmax; j++) {
        __syncthreads();
        const size_t kb = kvb0 + (size_t)j * 64 * 64;
#pragma unroll
        for (int i = 0; i < 2; i++) {
            const int idx = tid + i * 256;
            const int row = idx >> 3;
            const int c8  = (idx & 7) * 8;
            const int so  = row * VSTR + c8;
            const size_t go = kb + row * 64 + c8;
            *(uint4*)&sbuf[so]         = *(const uint4*)((const uint16_t*)g_kh + go);
            *(uint4*)&sbuf[4608 + so]  = *(const uint4*)((const uint16_t*)g_kl + go);
            *(uint4*)&sbuf[9216 + so]  = *(const uint4*)((const uint16_t*)g_vh + go);
            *(uint4*)&sbuf[13824 + so] = *(const uint4*)((const uint16_t*)g_vl + go);
        }
        __syncthreads();

        float S[8][4];
#pragma unroll
        for (int nt = 0; nt < 8; nt++)
#pragma unroll
            for (int q = 0; q < 4; q++) S[nt][q] = 0.f;

#pragma unroll
        for (int ks = 0; ks < 4; ks++) {
#pragma unroll
            for (int np = 0; np < 4; np++) {
                uint32_t KBh[4], KBl[4];
                const int off = (np * 16 + (grp >> 1) * 8 + lr) * VSTR + ks * 16 + (grp & 1) * 8;
                ldmx4(KBh, sb + (uint32_t)off * 2u);
                ldmx4(KBl, sb + (uint32_t)(off + 4608) * 2u);
                mma_bf16(S[np * 2], Qh[ks], KBh);
                mma_bf16(S[np * 2], Qh[ks], KBl);
                mma_bf16(S[np * 2], Ql[ks], KBh);
                mma_bf16(S[np * 2 + 1], Qh[ks], KBh + 2);
                mma_bf16(S[np * 2 + 1], Qh[ks], KBl + 2);
                mma_bf16(S[np * 2 + 1], Ql[ks], KBh + 2);
            }
        }

        if (j >= 2 * qt) {
#pragma unroll
            for (int nt = 0; nt < 8; nt++)
#pragma unroll
                for (int q = 0; q < 4; q++) {
                    const int col = j * 64 + nt * 8 + 2 * (lane & 3) + (q & 1);
                    const int row = row_lo_g + (q >> 1) * 8;
                    if (col > row) S[nt][q] = -1e30f;
                }
        }

        float vlo = -1e30f, vhi = -1e30f;
#pragma unroll
        for (int nt = 0; nt < 8; nt++) {
            vlo = fmaxf(vlo, fmaxf(S[nt][0], S[nt][1]));
            vhi = fmaxf(vhi, fmaxf(S[nt][2], S[nt][3]));
        }
        vlo = fmaxf(vlo, __shfl_xor_sync(0xffffffffu, vlo, 1));
        vlo = fmaxf(vlo, __shfl_xor_sync(0xffffffffu, vlo, 2));
        vhi = fmaxf(vhi, __shfl_xor_sync(0xffffffffu, vhi, 1));
        vhi = fmaxf(vhi, __shfl_xor_sync(0xffffffffu, vhi, 2));

        const float mn_lo = fmaxf(m_lo, vlo);
        const float mn_hi = fmaxf(m_hi, vhi);
        const float al = __expf(m_lo - mn_lo);
        const float ah = __expf(m_hi - mn_hi);
        m_lo = mn_lo; m_hi = mn_hi;

        float slo = 0.f, shi = 0.f;
#pragma unroll
        for (int nt = 0; nt < 8; nt++) {
            S[nt][0] = __expf(S[nt][0] - mn_lo);
            S[nt][1] = __expf(S[nt][1] - mn_lo);
            S[nt][2] = __expf(S[nt][2] - mn_hi);
            S[nt][3] = __expf(S[nt][3] - mn_hi);
            slo += S[nt][0] + S[nt][1];
            shi += S[nt][2] + S[nt][3];
        }
        slo += __shfl_xor_sync(0xffffffffu, slo, 1);
        slo += __shfl_xor_sync(0xffffffffu, slo, 2);
        shi += __shfl_xor_sync(0xffffffffu, shi, 1);
        shi += __shfl_xor_sync(0xffffffffu, shi, 2);
        l_lo = l_lo * al + slo;
        l_hi = l_hi * ah + shi;
#pragma unroll
        for (int nt = 0; nt < 8; nt++) {
            O[nt][0] *= al; O[nt][1] *= al;
            O[nt][2] *= ah; O[nt][3] *= ah;
        }

#pragma unroll
        for (int ks = 0; ks < 4; ks++) {
            uint32_t Ph[4], Pl[4];
            split2(S[2 * ks][0], S[2 * ks][1], Ph[0], Pl[0]);
            split2(S[2 * ks][2], S[2 * ks][3], Ph[1], Pl[1]);
            split2(S[2 * ks + 1][0], S[2 * ks + 1][1], Ph[2], Pl[2]);
            split2(S[2 * ks + 1][2], S[2 * ks + 1][3], Ph[3], Pl[3]);
#pragma unroll
            for (int np = 0; np < 4; np++) {
                uint32_t VBh[4], VBl[4];
                const int off = (ks * 16 + (grp & 1) * 8 + lr) * VSTR + np * 16 + (grp >> 1) * 8;
                ldmx4t(VBh, sb + (uint32_t)(9216 + off) * 2u);
                ldmx4t(VBl, sb + (uint32_t)(13824 + off) * 2u);
                mma_bf16(O[np * 2], Ph, VBh);
                mma_bf16(O[np * 2], Ph, VBl);
                mma_bf16(O[np * 2], Pl, VBh);
                mma_bf16(O[np * 2 + 1], Ph, VBh + 2);
                mma_bf16(O[np * 2 + 1], Ph, VBl + 2);
                mma_bf16(O[np * 2 + 1], Pl, VBh + 2);
            }
        }
    }

    // ---- epilogue: normalize, split to bf16 hi/lo, write [B,S,D] ----
    const float inv_lo = 1.0f / l_lo;
    const float inv_hi = 1.0f / l_hi;
    const int bb = bh >> 4, hh = bh & 15;
    const int col0 = hh * 64 + 2 * (lane & 3);
#pragma unroll
    for (int nt = 0; nt < 8; nt++) {
        const int col = col0 + nt * 8;
        uint32_t hw, lw;
        split2(O[nt][0] * inv_lo, O[nt][1] * inv_lo, hw, lw);
        const size_t i0 = ((size_t)bb * Sseq + row_lo_g) * Dm + col;
        *(uint32_t*)(g_oh + i0) = hw;
        *(uint32_t*)(g_ol + i0) = lw;
        split2(O[nt][2] * inv_hi, O[nt][3] * inv_hi, hw, lw);
        const size_t i1 = ((size_t)bb * Sseq + row_lo_g + 8) * Dm + col;
        *(uint32_t*)(g_oh + i1) = hw;
        *(uint32_t*)(g_ol + i1) = lw;
    }
}

// ---------------------------------------------------------------------------
// Launch
// ---------------------------------------------------------------------------
extern "C" void kernel_launch(void* const* d_in, const int* in_sizes, int n_in,
                              void* d_out, int out_size)
{
    const float* x  = (const float*)d_in[0];
    const float* Wq = (const float*)d_in[1];
    const float* bq = (const float*)d_in[2];
    const float* Wk = (const float*)d_in[3];
    const float* bk = (const float*)d_in[4];
    const float* Wv = (const float*)d_in[5];
    const float* bv = (const float*)d_in[6];
    const float* Wp = (const float*)d_in[7];
    const float* bp = (const float*)d_in[8];
    float* out = (float*)d_out;

    // one-shot hi/lo splits (dest globals bound in device code)
    split_kernel<0><<<(int)(XSZ / 8 / 256), 256>>>(x);
    split_kernel<1><<<(int)(WSZ / 8 / 256), 256>>>(Wq);
    split_kernel<2><<<(int)(WSZ / 8 / 256), 256>>>(Wk);
    split_kernel<3><<<(int)(WSZ / 8 / 256), 256>>>(Wv);
    split_kernel<4><<<(int)(WSZ / 8 / 256), 256>>>(Wp);

    qkv_gemm<<<dim3(Dm / 128, Mrows / 128, 3), 256>>>(bq, bk, bv);

    attn_mma<<<dim3(Sseq / 128, Bc * Hn), 256>>>();

    out_gemm<<<dim3(Dm / 128, Mrows / 128), 256>>>(bp, out);
}

// round 13
// speedup vs baseline: 2.7186x; 1.0480x over previous
#include <cuda_runtime.h>
#include <cuda_bf16.h>
#include <cstdint>

// ---------------------------------------------------------------------------
// Problem constants
// ---------------------------------------------------------------------------
constexpr int Bc   = 4;
constexpr int Sseq = 2048;
constexpr int Dm   = 1024;
constexpr int Hn   = 16;
constexpr int DHc  = 64;
constexpr int Mrows = Bc * Sseq;     // 8192
constexpr size_t HSD = (size_t)Bc * Hn * Sseq * DHc;   // 8,388,608
constexpr size_t XSZ = (size_t)Mrows * Dm;             // 8,388,608
constexpr size_t WSZ = (size_t)Dm * Dm;                // 1,048,576

// Device-global scratch (no cudaMalloc allowed); 16B-aligned for uint4/cp.async
__device__ __align__(16) __nv_bfloat16 g_qh[HSD], g_ql[HSD];   // Q hi/lo, scale folded
__device__ __align__(16) __nv_bfloat16 g_kh[HSD], g_kl[HSD];   // K hi/lo, quirk layout
__device__ __align__(16) __nv_bfloat16 g_vh[HSD], g_vl[HSD];   // V hi/lo
__device__ __align__(16) __nv_bfloat16 g_xh[XSZ], g_xl[XSZ];   // input x hi/lo
__device__ __align__(16) __nv_bfloat16 g_oh[XSZ], g_ol[XSZ];   // attention out hi/lo
__device__ __align__(16) __nv_bfloat16 g_wqh[WSZ], g_wql[WSZ];
__device__ __align__(16) __nv_bfloat16 g_wkh[WSZ], g_wkl[WSZ];
__device__ __align__(16) __nv_bfloat16 g_wvh[WSZ], g_wvl[WSZ];
__device__ __align__(16) __nv_bfloat16 g_wph[WSZ], g_wpl[WSZ];

// ---------------------------------------------------------------------------
// Helpers (baseline sm_80+ only)
// ---------------------------------------------------------------------------
static __device__ __forceinline__ uint32_t smem_u32(const void* p) {
    uint32_t a;
    asm("{ .reg .u64 t; cvta.to.shared.u64 t, %1; cvt.u32.u64 %0, t; }"
        : "=r"(a) : "l"(p));
    return a;
}

static __device__ __forceinline__ void ldmx4(uint32_t* r, uint32_t addr) {
    asm volatile("ldmatrix.sync.aligned.m8n8.x4.shared.b16 {%0,%1,%2,%3}, [%4];"
        : "=r"(r[0]), "=r"(r[1]), "=r"(r[2]), "=r"(r[3]) : "r"(addr));
}

static __device__ __forceinline__ void ldmx4t(uint32_t* r, uint32_t addr) {
    asm volatile("ldmatrix.sync.aligned.m8n8.x4.trans.shared.b16 {%0,%1,%2,%3}, [%4];"
        : "=r"(r[0]), "=r"(r[1]), "=r"(r[2]), "=r"(r[3]) : "r"(addr));
}

static __device__ __forceinline__ void mma_bf16(float* c, const uint32_t* a, const uint32_t* b) {
    asm volatile(
        "mma.sync.aligned.m16n8k16.row.col.f32.bf16.bf16.f32 "
        "{%0,%1,%2,%3}, {%4,%5,%6,%7}, {%8,%9}, {%0,%1,%2,%3};"
        : "+f"(c[0]), "+f"(c[1]), "+f"(c[2]), "+f"(c[3])
        : "r"(a[0]), "r"(a[1]), "r"(a[2]), "r"(a[3]), "r"(b[0]), "r"(b[1]));
}

#define CP_ASYNC16(dst, src) \
    asm volatile("cp.async.cg.shared.global [%0], [%1], 16;" :: "r"(dst), "l"(src))
#define CP_COMMIT() asm volatile("cp.async.commit_group;")
#define CP_WAIT1()  asm volatile("cp.async.wait_group 1;")
#define CP_WAIT0()  asm volatile("cp.async.wait_group 0;")

// f32 -> (bf16 hi, bf16 lo): hi = truncate, lo = rn(x - hi). Pack pairs (a=low half).
static __device__ __forceinline__ void split2(float a, float b, uint32_t& hw, uint32_t& lw) {
    uint32_t ua = __float_as_uint(a), ub = __float_as_uint(b);
    hw = (ua >> 16) | (ub & 0xFFFF0000u);
    float la = a - __uint_as_float(ua & 0xFFFF0000u);
    float lb = b - __uint_as_float(ub & 0xFFFF0000u);
    __nv_bfloat162 t = __floats2bfloat162_rn(la, lb);
    lw = *reinterpret_cast<uint32_t*>(&t);
}

static __device__ __forceinline__ void split1(float v, __nv_bfloat16& h, __nv_bfloat16& l) {
    uint32_t u = __float_as_uint(v) & 0xFFFF0000u;
    uint16_t hb = (uint16_t)(__float_as_uint(v) >> 16);
    h = *reinterpret_cast<__nv_bfloat16*>(&hb);
    l = __float2bfloat16(v - __uint_as_float(u));
}

// ---------------------------------------------------------------------------
// One-shot f32 -> bf16 hi/lo converters. Destination globals bound in device
// code (device symbols must never be passed as kernel args from host).
// ---------------------------------------------------------------------------
__global__ __launch_bounds__(256)
void split_x(const float* __restrict__ src)
{
    const size_t i = (size_t)blockIdx.x * 256 + threadIdx.x;
    const float4* p = (const float4*)src + 2 * i;
    float4 u = p[0], v = p[1];
    uint32_t h0, h1, h2, h3, l0, l1, l2, l3;
    split2(u.x, u.y, h0, l0); split2(u.z, u.w, h1, l1);
    split2(v.x, v.y, h2, l2); split2(v.z, v.w, h3, l3);
    ((uint4*)g_xh)[i] = make_uint4(h0, h1, h2, h3);
    ((uint4*)g_xl)[i] = make_uint4(l0, l1, l2, l3);
}

__global__ __launch_bounds__(256)
void split_w4(const float* __restrict__ Wq, const float* __restrict__ Wk,
              const float* __restrict__ Wv, const float* __restrict__ Wp)
{
    const int which = blockIdx.y;
    const float* src;
    __nv_bfloat16 *dh, *dl;
    if (which == 0)      { src = Wq; dh = g_wqh; dl = g_wql; }
    else if (which == 1) { src = Wk; dh = g_wkh; dl = g_wkl; }
    else if (which == 2) { src = Wv; dh = g_wvh; dl = g_wvl; }
    else                 { src = Wp; dh = g_wph; dl = g_wpl; }

    const size_t i = (size_t)blockIdx.x * 256 + threadIdx.x;
    const float4* p = (const float4*)src + 2 * i;
    float4 u = p[0], v = p[1];
    uint32_t h0, h1, h2, h3, l0, l1, l2, l3;
    split2(u.x, u.y, h0, l0); split2(u.z, u.w, h1, l1);
    split2(v.x, v.y, h2, l2); split2(v.z, v.w, h3, l3);
    ((uint4*)dh)[i] = make_uint4(h0, h1, h2, h3);
    ((uint4*)dl)[i] = make_uint4(l0, l1, l2, l3);
}

// ---------------------------------------------------------------------------
// GEMM mainloop: cp.async 2-stage double-buffered, pre-split bf16 inputs.
// CTA tile 128x128, 8 warps (2x4), warp tile 64x32, K-chunk 32.
// Dynamic smem: [2 buffers][4 tiles][TILE_E elems]
// ---------------------------------------------------------------------------
constexpr int SSTR   = 40;            // smem row stride in bf16 elems (80B, LDSM-clean)
constexpr int TILE_E = 128 * SSTR;    // 5120
constexpr int GEMM_SMEM = 2 * 4 * TILE_E * 2;   // 81,920 B

static __device__ __forceinline__ void gemm_mainloop_pipe(
    float c4[4][4][4],
    const uint16_t* __restrict__ srcA_h, const uint16_t* __restrict__ srcA_l,
    const uint16_t* __restrict__ srcB_h, const uint16_t* __restrict__ srcB_l,
    uint32_t sb, int bm, int bn, int tid, int baseA, int baseB)
{
    const uint16_t* const srcs[4] = {srcA_h, srcA_l, srcB_h, srcB_l};

    auto issue = [&](int c, int buf) {
#pragma unroll
        for (int t = 0; t < 8; t++) {
            const int idx  = tid + t * 256;       // 0..2047
            const int tile = idx >> 9;            // 0..3
            const int r    = (idx >> 2) & 127;
            const int g    = idx & 3;
            const uint32_t dst = sb +
                (uint32_t)((buf * 4 + tile) * TILE_E + r * SSTR + g * 8) * 2u;
            const int rowg = (tile < 2 ? bm : bn) + r;
            CP_ASYNC16(dst, srcs[tile] + (size_t)rowg * Dm + c * 32 + g * 8);
        }
        CP_COMMIT();
    };

    issue(0, 0);

    for (int c = 0; c < 32; c++) {
        const int buf = c & 1;
        if (c + 1 < 32) { issue(c + 1, buf ^ 1); CP_WAIT1(); }
        else            { CP_WAIT0(); }
        __syncthreads();

        const uint32_t aAh = sb + (uint32_t)((buf * 4 + 0) * TILE_E) * 2u;
        const uint32_t aAl = sb + (uint32_t)((buf * 4 + 1) * TILE_E) * 2u;
        const uint32_t aBh = sb + (uint32_t)((buf * 4 + 2) * TILE_E) * 2u;
        const uint32_t aBl = sb + (uint32_t)((buf * 4 + 3) * TILE_E) * 2u;

#pragma unroll
        for (int ks = 0; ks < 32; ks += 16) {
            uint32_t Bh[8], Bl[8];
#pragma unroll
            for (int p = 0; p < 2; p++) {
                const uint32_t off = (uint32_t)(baseB + p * 16 * SSTR + ks) * 2u;
                ldmx4(&Bh[p * 4], aBh + off);
                ldmx4(&Bl[p * 4], aBl + off);
            }
#pragma unroll
            for (int mt = 0; mt < 4; mt++) {
                uint32_t Ahf[4], Alf[4];
                const uint32_t off = (uint32_t)(baseA + mt * 16 * SSTR + ks) * 2u;
                ldmx4(Ahf, aAh + off);
                ldmx4(Alf, aAl + off);
#pragma unroll
                for (int nt = 0; nt < 4; nt++) {
                    mma_bf16(c4[mt][nt], Ahf, &Bh[nt * 2]);
                    mma_bf16(c4[mt][nt], Ahf, &Bl[nt * 2]);
                    mma_bf16(c4[mt][nt], Alf, &Bh[nt * 2]);
                }
            }
        }
        __syncthreads();   // protects buf reuse by the next issue
    }
}

// ---------------------------------------------------------------------------
// Fused QKV projection: gridDim.z selects {Q, K, V}
// ---------------------------------------------------------------------------
__global__ __launch_bounds__(256, 2)
void qkv_gemm(const float* __restrict__ bq, const float* __restrict__ bk,
              const float* __restrict__ bv)
{
    extern __shared__ __align__(16) uint16_t dynsmem[];
    const uint32_t sb = smem_u32(dynsmem);

    const int tid  = threadIdx.x;
    const int lane = tid & 31;
    const int wid  = tid >> 5;
    const int wm   = wid >> 2;
    const int wn   = wid & 3;
    const int bm   = blockIdx.y * 128;
    const int bn   = blockIdx.x * 128;
    const int z    = blockIdx.z;        // 0=Q, 1=K, 2=V

    const __nv_bfloat16 *wh, *wl;
    const float* bias;
    if (z == 0)      { wh = g_wqh; wl = g_wql; bias = bq; }
    else if (z == 1) { wh = g_wkh; wl = g_wkl; bias = bk; }
    else             { wh = g_wvh; wl = g_wvl; bias = bv; }

    const int grp = lane >> 3, lr = lane & 7;
    const int baseA = (wm * 64 + (grp & 1) * 8 + lr) * SSTR + (grp >> 1) * 8;
    const int baseB = (wn * 32 + (grp >> 1) * 8 + lr) * SSTR + (grp & 1) * 8;

    float c4[4][4][4];
#pragma unroll
    for (int mt = 0; mt < 4; mt++)
#pragma unroll
        for (int nt = 0; nt < 4; nt++)
#pragma unroll
            for (int q = 0; q < 4; q++) c4[mt][nt][q] = 0.f;

    gemm_mainloop_pipe(c4, (const uint16_t*)g_xh, (const uint16_t*)g_xl,
                       (const uint16_t*)wh, (const uint16_t*)wl,
                       sb, bm, bn, tid, baseA, baseB);

    // ---- epilogue: +bias, per-z scatter ----
#pragma unroll
    for (int mt = 0; mt < 4; mt++) {
#pragma unroll
        for (int nt = 0; nt < 4; nt++) {
            const float* cc = c4[mt][nt];
            const int m0 = bm + wm * 64 + mt * 16 + (lane >> 2);
            const int n0 = bn + wn * 32 + nt * 8 + 2 * (lane & 3);
            const float b0 = __ldg(&bias[n0]);
            const float b1 = __ldg(&bias[n0 + 1]);
#pragma unroll
            for (int h = 0; h < 2; h++) {
                const int m  = m0 + h * 8;
                float v0 = cc[h * 2 + 0] + b0;
                float v1 = cc[h * 2 + 1] + b1;
                const int bb = m >> 11;
                const int ss = m & 2047;
                if (z == 1) {   // K quirk: h = n%16, d = n/16
                    __nv_bfloat16 h0, l0, h1, l1;
                    split1(v0, h0, l0); split1(v1, h1, l1);
                    const size_t i0 = (((size_t)(bb * Hn + (n0 & 15)) * Sseq + ss) << 6) + (n0 >> 4);
                    const size_t i1 = (((size_t)(bb * Hn + ((n0 + 1) & 15)) * Sseq + ss) << 6) + ((n0 + 1) >> 4);
                    g_kh[i0] = h0; g_kl[i0] = l0;
                    g_kh[i1] = h1; g_kl[i1] = l1;
                } else {
                    if (z == 0) { v0 *= 0.125f; v1 *= 0.125f; }   // fold softmax scale
                    uint32_t hw, lw;
                    split2(v0, v1, hw, lw);
                    const size_t idx = (((size_t)(bb * Hn + (n0 >> 6)) * Sseq + ss) << 6) + (n0 & 63);
                    __nv_bfloat16* dh = (z == 0) ? g_qh : g_vh;
                    __nv_bfloat16* dl = (z == 0) ? g_ql : g_vl;
                    *(uint32_t*)(dh + idx) = hw;
                    *(uint32_t*)(dl + idx) = lw;
                }
            }
        }
    }
}

// ---------------------------------------------------------------------------
// Final projection: out = O @ Wp^T + bp  (f32 output)
// ---------------------------------------------------------------------------
__global__ __launch_bounds__(256, 2)
void out_gemm(const float* __restrict__ bias, float* __restrict__ Cout)
{
    extern __shared__ __align__(16) uint16_t dynsmem[];
    const uint32_t sb = smem_u32(dynsmem);

    const int tid  = threadIdx.x;
    const int lane = tid & 31;
    const int wid  = tid >> 5;
    const int wm   = wid >> 2;
    const int wn   = wid & 3;
    const int bm   = blockIdx.y * 128;
    const int bn   = blockIdx.x * 128;

    const int grp = lane >> 3, lr = lane & 7;
    const int baseA = (wm * 64 + (grp & 1) * 8 + lr) * SSTR + (grp >> 1) * 8;
    const int baseB = (wn * 32 + (grp >> 1) * 8 + lr) * SSTR + (grp & 1) * 8;

    float c4[4][4][4];
#pragma unroll
    for (int mt = 0; mt < 4; mt++)
#pragma unroll
        for (int nt = 0; nt < 4; nt++)
#pragma unroll
            for (int q = 0; q < 4; q++) c4[mt][nt][q] = 0.f;

    gemm_mainloop_pipe(c4, (const uint16_t*)g_oh, (const uint16_t*)g_ol,
                       (const uint16_t*)g_wph, (const uint16_t*)g_wpl,
                       sb, bm, bn, tid, baseA, baseB);

#pragma unroll
    for (int mt = 0; mt < 4; mt++) {
#pragma unroll
        for (int nt = 0; nt < 4; nt++) {
            const float* cc = c4[mt][nt];
            const int m0 = bm + wm * 64 + mt * 16 + (lane >> 2);
            const int n0 = bn + wn * 32 + nt * 8 + 2 * (lane & 3);
            const float b0 = __ldg(&bias[n0]);
            const float b1 = __ldg(&bias[n0 + 1]);
#pragma unroll
            for (int h = 0; h < 2; h++) {
                const int m = m0 + h * 8;
                *(float2*)(Cout + (size_t)m * Dm + n0) =
                    make_float2(cc[h * 2 + 0] + b0, cc[h * 2 + 1] + b1);
            }
        }
    }
}

// ---------------------------------------------------------------------------
// Flash attention via mma.sync bf16 hi/lo, cp.async double-buffered KV.
// Block = 256 thr / 8 warps; q-tile 128, kv-tile 64; one (b,h) per blockIdx.y.
// Dynamic smem: 2 buffers x 4 tiles x 64 x VSTR bf16 = 73,728 B.
// ---------------------------------------------------------------------------
constexpr int VSTR = 72;
constexpr int ABUF_E = 4 * 64 * VSTR;              // 18,432 elems per buffer
constexpr int ATTN_SMEM = 2 * ABUF_E * 2;          // 73,728 B

__global__ __launch_bounds__(256, 2)
void attn_mma()
{
    extern __shared__ __align__(16) uint16_t dynsmem[];
    uint16_t* sbuf = dynsmem;
    const int tid  = threadIdx.x;
    const int lane = tid & 31;
    const int w    = tid >> 5;
    const int qt   = (int)gridDim.x - 1 - (int)blockIdx.x;   // heavy blocks first
    const int bh   = blockIdx.y;
    const int grp  = lane >> 3, lr = lane & 7;
    const uint32_t sb = smem_u32(sbuf);

    // ---- stage Q hi/lo into buffer 0, load A-fragments, release smem ----
    const size_t qbase = ((size_t)bh * Sseq + (size_t)qt * 128) * 64;
#pragma unroll
    for (int i = 0; i < 4; i++) {
        const int idx = tid + i * 256;      // 0..1023
        const int row = idx >> 3;
        const int c8  = (idx & 7) * 8;
        *(uint4*)&sbuf[row * VSTR + c8]        = *(const uint4*)((const uint16_t*)g_qh + qbase + row * 64 + c8);
        *(uint4*)&sbuf[9216 + row * VSTR + c8] = *(const uint4*)((const uint16_t*)g_ql + qbase + row * 64 + c8);
    }
    __syncthreads();
    uint32_t Qh[4][4], Ql[4][4];
#pragma unroll
    for (int ks = 0; ks < 4; ks++) {
        const int off = (w * 16 + (grp & 1) * 8 + lr) * VSTR + ks * 16 + (grp >> 1) * 8;
        ldmx4(Qh[ks], sb + (uint32_t)off * 2u);
        ldmx4(Ql[ks], sb + (uint32_t)(off + 9216) * 2u);
    }
    __syncthreads();   // all warps done reading Q staging before kv overwrites buf0

    float O[8][4];
#pragma unroll
    for (int nt = 0; nt < 8; nt++)
#pragma unroll
        for (int q = 0; q < 4; q++) O[nt][q] = 0.f;
    float m_lo = -1e30f, m_hi = -1e30f, l_lo = 0.f, l_hi = 0.f;

    const int row_lo_g = qt * 128 + w * 16 + (lane >> 2);   // global q row (lo half)
    const size_t kvb0 = (size_t)bh * Sseq * 64;
    const int jmax = 2 * qt + 1;

    auto issue_kv = [&](int j, int buf) {
        const size_t kb = kvb0 + (size_t)j * 64 * 64;
        const int boff = buf * ABUF_E;
#pragma unroll
        for (int i = 0; i < 2; i++) {
            const int idx = tid + i * 256;      // 0..511
            const int row = idx >> 3;
            const int c8  = (idx & 7) * 8;
            const int so  = row * VSTR + c8;
            const size_t go = kb + row * 64 + c8;
            CP_ASYNC16(sb + (uint32_t)(boff + so) * 2u,          (const uint16_t*)g_kh + go);
            CP_ASYNC16(sb + (uint32_t)(boff + 4608 + so) * 2u,   (const uint16_t*)g_kl + go);
            CP_ASYNC16(sb + (uint32_t)(boff + 9216 + so) * 2u,   (const uint16_t*)g_vh + go);
            CP_ASYNC16(sb + (uint32_t)(boff + 13824 + so) * 2u,  (const uint16_t*)g_vl + go);
        }
        CP_COMMIT();
    };

    issue_kv(0, 0);

    for (int j = 0; j <= jmax; j++) {
        const int buf = j & 1;
        if (j + 1 <= jmax) { issue_kv(j + 1, buf ^ 1); CP_WAIT1(); }
        else               { CP_WAIT0(); }
        __syncthreads();
        const uint32_t boff = (uint32_t)(buf * ABUF_E);

        // ---- S = Q @ K^T (hi/lo 3-term) ----
        float S[8][4];
#pragma unroll
        for (int nt = 0; nt < 8; nt++)
#pragma unroll
            for (int q = 0; q < 4; q++) S[nt][q] = 0.f;

#pragma unroll
        for (int ks = 0; ks < 4; ks++) {
#pragma unroll
            for (int np = 0; np < 4; np++) {
                uint32_t KBh[4], KBl[4];
                const uint32_t off = boff + (uint32_t)((np * 16 + (grp >> 1) * 8 + lr) * VSTR + ks * 16 + (grp & 1) * 8);
                ldmx4(KBh, sb + off * 2u);
                ldmx4(KBl, sb + (off + 4608u) * 2u);
                mma_bf16(S[np * 2], Qh[ks], KBh);
                mma_bf16(S[np * 2], Qh[ks], KBl);
                mma_bf16(S[np * 2], Ql[ks], KBh);
                mma_bf16(S[np * 2 + 1], Qh[ks], KBh + 2);
                mma_bf16(S[np * 2 + 1], Qh[ks], KBl + 2);
                mma_bf16(S[np * 2 + 1], Ql[ks], KBh + 2);
            }
        }

        // ---- causal mask (last two kv tiles only) ----
        if (j >= 2 * qt) {
#pragma unroll
            for (int nt = 0; nt < 8; nt++)
#pragma unroll
                for (int q = 0; q < 4; q++) {
                    const int col = j * 64 + nt * 8 + 2 * (lane & 3) + (q & 1);
                    const int row = row_lo_g + (q >> 1) * 8;
                    if (col > row) S[nt][q] = -1e30f;
                }
        }

        // ---- online softmax ----
        float vlo = -1e30f, vhi = -1e30f;
#pragma unroll
        for (int nt = 0; nt < 8; nt++) {
            vlo = fmaxf(vlo, fmaxf(S[nt][0], S[nt][1]));
            vhi = fmaxf(vhi, fmaxf(S[nt][2], S[nt][3]));
        }
        vlo = fmaxf(vlo, __shfl_xor_sync(0xffffffffu, vlo, 1));
        vlo = fmaxf(vlo, __shfl_xor_sync(0xffffffffu, vlo, 2));
        vhi = fmaxf(vhi, __shfl_xor_sync(0xffffffffu, vhi, 1));
        vhi = fmaxf(vhi, __shfl_xor_sync(0xffffffffu, vhi, 2));

        const float mn_lo = fmaxf(m_lo, vlo);
        const float mn_hi = fmaxf(m_hi, vhi);
        const float al = __expf(m_lo - mn_lo);
        const float ah = __expf(m_hi - mn_hi);
        m_lo = mn_lo; m_hi = mn_hi;

        float slo = 0.f, shi = 0.f;
#pragma unroll
        for (int nt = 0; nt < 8; nt++) {
            S[nt][0] = __expf(S[nt][0] - mn_lo);
            S[nt][1] = __expf(S[nt][1] - mn_lo);
            S[nt][2] = __expf(S[nt][2] - mn_hi);
            S[nt][3] = __expf(S[nt][3] - mn_hi);
            slo += S[nt][0] + S[nt][1];
            shi += S[nt][2] + S[nt][3];
        }
        slo += __shfl_xor_sync(0xffffffffu, slo, 1);
        slo += __shfl_xor_sync(0xffffffffu, slo, 2);
        shi += __shfl_xor_sync(0xffffffffu, shi, 1);
        shi += __shfl_xor_sync(0xffffffffu, shi, 2);
        l_lo = l_lo * al + slo;
        l_hi = l_hi * ah + shi;
#pragma unroll
        for (int nt = 0; nt < 8; nt++) {
            O[nt][0] *= al; O[nt][1] *= al;
            O[nt][2] *= ah; O[nt][3] *= ah;
        }

        // ---- O += P @ V (P from registers, V via ldmatrix.trans) ----
#pragma unroll
        for (int ks = 0; ks < 4; ks++) {
            uint32_t Ph[4], Pl[4];
            split2(S[2 * ks][0], S[2 * ks][1], Ph[0], Pl[0]);
            split2(S[2 * ks][2], S[2 * ks][3], Ph[1], Pl[1]);
            split2(S[2 * ks + 1][0], S[2 * ks + 1][1], Ph[2], Pl[2]);
            split2(S[2 * ks + 1][2], S[2 * ks + 1][3], Ph[3], Pl[3]);
#pragma unroll
            for (int np = 0; np < 4; np++) {
                uint32_t VBh[4], VBl[4];
                const uint32_t off = boff + (uint32_t)((ks * 16 + (grp & 1) * 8 + lr) * VSTR + np * 16 + (grp >> 1) * 8);
                ldmx4t(VBh, sb + (off + 9216u) * 2u);
                ldmx4t(VBl, sb + (off + 13824u) * 2u);
                mma_bf16(O[np * 2], Ph, VBh);
                mma_bf16(O[np * 2], Ph, VBl);
                mma_bf16(O[np * 2], Pl, VBh);
                mma_bf16(O[np * 2 + 1], Ph, VBh + 2);
                mma_bf16(O[np * 2 + 1], Ph, VBl + 2);
                mma_bf16(O[np * 2 + 1], Pl, VBh + 2);
            }
        }
        __syncthreads();   // protects buf reuse by the next issue
    }

    // ---- epilogue: normalize, split to bf16 hi/lo, write [B,S,D] ----
    const float inv_lo = 1.0f / l_lo;
    const float inv_hi = 1.0f / l_hi;
    const int bb = bh >> 4, hh = bh & 15;
    const int col0 = hh * 64 + 2 * (lane & 3);
#pragma unroll
    for (int nt = 0; nt < 8; nt++) {
        const int col = col0 + nt * 8;
        uint32_t hw, lw;
        split2(O[nt][0] * inv_lo, O[nt][1] * inv_lo, hw, lw);
        const size_t i0 = ((size_t)bb * Sseq + row_lo_g) * Dm + col;
        *(uint32_t*)(g_oh + i0) = hw;
        *(uint32_t*)(g_ol + i0) = lw;
        split2(O[nt][2] * inv_hi, O[nt][3] * inv_hi, hw, lw);
        const size_t i1 = ((size_t)bb * Sseq + row_lo_g + 8) * Dm + col;
        *(uint32_t*)(g_oh + i1) = hw;
        *(uint32_t*)(g_ol + i1) = lw;
    }
}

// ---------------------------------------------------------------------------
// Launch
// ---------------------------------------------------------------------------
extern "C" void kernel_launch(void* const* d_in, const int* in_sizes, int n_in,
                              void* d_out, int out_size)
{
    const float* x  = (const float*)d_in[0];
    const float* Wq = (const float*)d_in[1];
    const float* bq = (const float*)d_in[2];
    const float* Wk = (const float*)d_in[3];
    const float* bk = (const float*)d_in[4];
    const float* Wv = (const float*)d_in[5];
    const float* bv = (const float*)d_in[6];
    const float* Wp = (const float*)d_in[7];
    const float* bp = (const float*)d_in[8];
    float* out = (float*)d_out;

    cudaFuncSetAttribute(qkv_gemm, cudaFuncAttributeMaxDynamicSharedMemorySize, GEMM_SMEM);
    cudaFuncSetAttribute(out_gemm, cudaFuncAttributeMaxDynamicSharedMemorySize, GEMM_SMEM);
    cudaFuncSetAttribute(attn_mma, cudaFuncAttributeMaxDynamicSharedMemorySize, ATTN_SMEM);

    // one-shot hi/lo splits (dest globals bound in device code)
    split_x<<<(int)(XSZ / 8 / 256), 256>>>(x);
    split_w4<<<dim3((int)(WSZ / 8 / 256), 4), 256>>>(Wq, Wk, Wv, Wp);

    qkv_gemm<<<dim3(Dm / 128, Mrows / 128, 3), 256, GEMM_SMEM>>>(bq, bk, bv);

    attn_mma<<<dim3(Sseq / 128, Bc * Hn), 256, ATTN_SMEM>>>();

    out_gemm<<<dim3(Dm / 128, Mrows / 128), 256, GEMM_SMEM>>>(bp, out);
}

// round 17
// speedup vs baseline: 2.8268x; 1.0398x over previous
#include <cuda_runtime.h>
#include <cuda_bf16.h>
#include <cstdint>

// ---------------------------------------------------------------------------
// Problem constants
// ---------------------------------------------------------------------------
constexpr int Bc   = 4;
constexpr int Sseq = 2048;
constexpr int Dm   = 1024;
constexpr int Hn   = 16;
constexpr int DHc  = 64;
constexpr int Mrows = Bc * Sseq;     // 8192
constexpr size_t HSD = (size_t)Bc * Hn * Sseq * DHc;   // 8,388,608
constexpr size_t XSZ = (size_t)Mrows * Dm;             // 8,388,608
constexpr size_t WSZ = (size_t)Dm * Dm;                // 1,048,576

// Device-global scratch (no cudaMalloc allowed); 16B-aligned for uint4/cp.async
__device__ __align__(16) __nv_bfloat16 g_qh[HSD], g_ql[HSD];   // Q hi/lo, scale folded
__device__ __align__(16) __nv_bfloat16 g_kh[HSD], g_kl[HSD];   // K hi/lo, quirk layout
__device__ __align__(16) __nv_bfloat16 g_vh[HSD], g_vl[HSD];   // V hi/lo
__device__ __align__(16) __nv_bfloat16 g_xh[XSZ], g_xl[XSZ];   // input x hi/lo
__device__ __align__(16) __nv_bfloat16 g_oh[XSZ], g_ol[XSZ];   // attention out hi/lo
__device__ __align__(16) __nv_bfloat16 g_wqh[WSZ], g_wql[WSZ];
__device__ __align__(16) __nv_bfloat16 g_wkh[WSZ], g_wkl[WSZ];
__device__ __align__(16) __nv_bfloat16 g_wvh[WSZ], g_wvl[WSZ];
__device__ __align__(16) __nv_bfloat16 g_wph[WSZ], g_wpl[WSZ];

// ---------------------------------------------------------------------------
// Helpers (baseline sm_80+ only)
// ---------------------------------------------------------------------------
static __device__ __forceinline__ uint32_t smem_u32(const void* p) {
    uint32_t a;
    asm("{ .reg .u64 t; cvta.to.shared.u64 t, %1; cvt.u32.u64 %0, t; }"
        : "=r"(a) : "l"(p));
    return a;
}

static __device__ __forceinline__ void ldmx4(uint32_t* r, uint32_t addr) {
    asm volatile("ldmatrix.sync.aligned.m8n8.x4.shared.b16 {%0,%1,%2,%3}, [%4];"
        : "=r"(r[0]), "=r"(r[1]), "=r"(r[2]), "=r"(r[3]) : "r"(addr));
}

static __device__ __forceinline__ void ldmx4t(uint32_t* r, uint32_t addr) {
    asm volatile("ldmatrix.sync.aligned.m8n8.x4.trans.shared.b16 {%0,%1,%2,%3}, [%4];"
        : "=r"(r[0]), "=r"(r[1]), "=r"(r[2]), "=r"(r[3]) : "r"(addr));
}

static __device__ __forceinline__ void mma_bf16(float* c, const uint32_t* a, const uint32_t* b) {
    asm volatile(
        "mma.sync.aligned.m16n8k16.row.col.f32.bf16.bf16.f32 "
        "{%0,%1,%2,%3}, {%4,%5,%6,%7}, {%8,%9}, {%0,%1,%2,%3};"
        : "+f"(c[0]), "+f"(c[1]), "+f"(c[2]), "+f"(c[3])
        : "r"(a[0]), "r"(a[1]), "r"(a[2]), "r"(a[3]), "r"(b[0]), "r"(b[1]));
}

#define CP_ASYNC16(dst, src) \
    asm volatile("cp.async.cg.shared.global [%0], [%1], 16;" :: "r"(dst), "l"(src))
#define CP_COMMIT() asm volatile("cp.async.commit_group;")
#define CP_WAIT1()  asm volatile("cp.async.wait_group 1;")
#define CP_WAIT0()  asm volatile("cp.async.wait_group 0;")

// f32 -> (bf16 hi, bf16 lo): hi = truncate, lo = rn(x - hi). Pack pairs (a=low half).
static __device__ __forceinline__ void split2(float a, float b, uint32_t& hw, uint32_t& lw) {
    uint32_t ua = __float_as_uint(a), ub = __float_as_uint(b);
    hw = (ua >> 16) | (ub & 0xFFFF0000u);
    float la = a - __uint_as_float(ua & 0xFFFF0000u);
    float lb = b - __uint_as_float(ub & 0xFFFF0000u);
    __nv_bfloat162 t = __floats2bfloat162_rn(la, lb);
    lw = *reinterpret_cast<uint32_t*>(&t);
}

static __device__ __forceinline__ void split1(float v, __nv_bfloat16& h, __nv_bfloat16& l) {
    uint32_t u = __float_as_uint(v) & 0xFFFF0000u;
    uint16_t hb = (uint16_t)(__float_as_uint(v) >> 16);
    h = *reinterpret_cast<__nv_bfloat16*>(&hb);
    l = __float2bfloat16(v - __uint_as_float(u));
}

// ---------------------------------------------------------------------------
// One-shot f32 -> bf16 hi/lo converters. Destination globals bound in device
// code (device symbols must never be passed as kernel args from host).
// ---------------------------------------------------------------------------
__global__ __launch_bounds__(256)
void split_x(const float* __restrict__ src)
{
    const size_t i = (size_t)blockIdx.x * 256 + threadIdx.x;
    const float4* p = (const float4*)src + 2 * i;
    float4 u = p[0], v = p[1];
    uint32_t h0, h1, h2, h3, l0, l1, l2, l3;
    split2(u.x, u.y, h0, l0); split2(u.z, u.w, h1, l1);
    split2(v.x, v.y, h2, l2); split2(v.z, v.w, h3, l3);
    ((uint4*)g_xh)[i] = make_uint4(h0, h1, h2, h3);
    ((uint4*)g_xl)[i] = make_uint4(l0, l1, l2, l3);
}

__global__ __launch_bounds__(256)
void split_w4(const float* __restrict__ Wq, const float* __restrict__ Wk,
              const float* __restrict__ Wv, const float* __restrict__ Wp)
{
    const int which = blockIdx.y;
    const float* src;
    __nv_bfloat16 *dh, *dl;
    if (which == 0)      { src = Wq; dh = g_wqh; dl = g_wql; }
    else if (which == 1) { src = Wk; dh = g_wkh; dl = g_wkl; }
    else if (which == 2) { src = Wv; dh = g_wvh; dl = g_wvl; }
    else                 { src = Wp; dh = g_wph; dl = g_wpl; }

    const size_t i = (size_t)blockIdx.x * 256 + threadIdx.x;
    const float4* p = (const float4*)src + 2 * i;
    float4 u = p[0], v = p[1];
    uint32_t h0, h1, h2, h3, l0, l1, l2, l3;
    split2(u.x, u.y, h0, l0); split2(u.z, u.w, h1, l1);
    split2(v.x, v.y, h2, l2); split2(v.z, v.w, h3, l3);
    ((uint4*)dh)[i] = make_uint4(h0, h1, h2, h3);
    ((uint4*)dl)[i] = make_uint4(l0, l1, l2, l3);
}

// ---------------------------------------------------------------------------
// GEMM mainloop: cp.async 2-stage double-buffered, pre-split bf16 inputs.
// CTA tile 128x128, 8 warps (2x4), warp tile 64x32, K-chunk 32.
// MMA ordering is term-major for accumulator ILP (reuse distance 4).
// ---------------------------------------------------------------------------
constexpr int SSTR   = 40;            // smem row stride in bf16 elems (80B, LDSM-clean)
constexpr int TILE_E = 128 * SSTR;    // 5120
constexpr int GEMM_SMEM = 2 * 4 * TILE_E * 2;   // 81,920 B

static __device__ __forceinline__ void gemm_mainloop_pipe(
    float c4[4][4][4],
    const uint16_t* __restrict__ srcA_h, const uint16_t* __restrict__ srcA_l,
    const uint16_t* __restrict__ srcB_h, const uint16_t* __restrict__ srcB_l,
    uint32_t sb, int bm, int bn, int tid, int baseA, int baseB)
{
    const uint16_t* const srcs[4] = {srcA_h, srcA_l, srcB_h, srcB_l};

    auto issue = [&](int c, int buf) {
#pragma unroll
        for (int t = 0; t < 8; t++) {
            const int idx  = tid + t * 256;       // 0..2047
            const int tile = idx >> 9;            // 0..3
            const int r    = (idx >> 2) & 127;
            const int g    = idx & 3;
            const uint32_t dst = sb +
                (uint32_t)((buf * 4 + tile) * TILE_E + r * SSTR + g * 8) * 2u;
            const int rowg = (tile < 2 ? bm : bn) + r;
            CP_ASYNC16(dst, srcs[tile] + (size_t)rowg * Dm + c * 32 + g * 8);
        }
        CP_COMMIT();
    };

    issue(0, 0);

    for (int c = 0; c < 32; c++) {
        const int buf = c & 1;
        if (c + 1 < 32) { issue(c + 1, buf ^ 1); CP_WAIT1(); }
        else            { CP_WAIT0(); }
        __syncthreads();

        const uint32_t aAh = sb + (uint32_t)((buf * 4 + 0) * TILE_E) * 2u;
        const uint32_t aAl = sb + (uint32_t)((buf * 4 + 1) * TILE_E) * 2u;
        const uint32_t aBh = sb + (uint32_t)((buf * 4 + 2) * TILE_E) * 2u;
        const uint32_t aBl = sb + (uint32_t)((buf * 4 + 3) * TILE_E) * 2u;

#pragma unroll
        for (int ks = 0; ks < 32; ks += 16) {
            uint32_t Bh[8], Bl[8];
#pragma unroll
            for (int p = 0; p < 2; p++) {
                const uint32_t off = (uint32_t)(baseB + p * 16 * SSTR + ks) * 2u;
                ldmx4(&Bh[p * 4], aBh + off);
                ldmx4(&Bl[p * 4], aBl + off);
            }
#pragma unroll
            for (int mt = 0; mt < 4; mt++) {
                uint32_t Ahf[4], Alf[4];
                const uint32_t off = (uint32_t)(baseA + mt * 16 * SSTR + ks) * 2u;
                ldmx4(Ahf, aAh + off);
                ldmx4(Alf, aAl + off);
                // term-major: accumulator reuse distance = 4
#pragma unroll
                for (int nt = 0; nt < 4; nt++) mma_bf16(c4[mt][nt], Ahf, &Bh[nt * 2]);
#pragma unroll
                for (int nt = 0; nt < 4; nt++) mma_bf16(c4[mt][nt], Ahf, &Bl[nt * 2]);
#pragma unroll
                for (int nt = 0; nt < 4; nt++) mma_bf16(c4[mt][nt], Alf, &Bh[nt * 2]);
            }
        }
        __syncthreads();   // protects buf reuse by the next issue
    }
}

// ---------------------------------------------------------------------------
// Fused QKV projection: gridDim.z selects {Q, K, V}
// ---------------------------------------------------------------------------
__global__ __launch_bounds__(256, 2)
void qkv_gemm(const float* __restrict__ bq, const float* __restrict__ bk,
              const float* __restrict__ bv)
{
    extern __shared__ __align__(16) uint16_t dynsmem[];
    const uint32_t sb = smem_u32(dynsmem);

    const int tid  = threadIdx.x;
    const int lane = tid & 31;
    const int wid  = tid >> 5;
    const int wm   = wid >> 2;
    const int wn   = wid & 3;
    const int bm   = blockIdx.y * 128;
    const int bn   = blockIdx.x * 128;
    const int z    = blockIdx.z;        // 0=Q, 1=K, 2=V

    const __nv_bfloat16 *wh, *wl;
    const float* bias;
    if (z == 0)      { wh = g_wqh; wl = g_wql; bias = bq; }
    else if (z == 1) { wh = g_wkh; wl = g_wkl; bias = bk; }
    else             { wh = g_wvh; wl = g_wvl; bias = bv; }

    const int grp = lane >> 3, lr = lane & 7;
    const int baseA = (wm * 64 + (grp & 1) * 8 + lr) * SSTR + (grp >> 1) * 8;
    const int baseB = (wn * 32 + (grp >> 1) * 8 + lr) * SSTR + (grp & 1) * 8;

    float c4[4][4][4];
#pragma unroll
    for (int mt = 0; mt < 4; mt++)
#pragma unroll
        for (int nt = 0; nt < 4; nt++)
#pragma unroll
            for (int q = 0; q < 4; q++) c4[mt][nt][q] = 0.f;

    gemm_mainloop_pipe(c4, (const uint16_t*)g_xh, (const uint16_t*)g_xl,
                       (const uint16_t*)wh, (const uint16_t*)wl,
                       sb, bm, bn, tid, baseA, baseB);

    // ---- epilogue: +bias, per-z scatter ----
#pragma unroll
    for (int mt = 0; mt < 4; mt++) {
#pragma unroll
        for (int nt = 0; nt < 4; nt++) {
            const float* cc = c4[mt][nt];
            const int m0 = bm + wm * 64 + mt * 16 + (lane >> 2);
            const int n0 = bn + wn * 32 + nt * 8 + 2 * (lane & 3);
            const float b0 = __ldg(&bias[n0]);
            const float b1 = __ldg(&bias[n0 + 1]);
#pragma unroll
            for (int h = 0; h < 2; h++) {
                const int m  = m0 + h * 8;
                float v0 = cc[h * 2 + 0] + b0;
                float v1 = cc[h * 2 + 1] + b1;
                const int bb = m >> 11;
                const int ss = m & 2047;
                if (z == 1) {   // K quirk: h = n%16, d = n/16
                    __nv_bfloat16 h0, l0, h1, l1;
                    split1(v0, h0, l0); split1(v1, h1, l1);
                    const size_t i0 = (((size_t)(bb * Hn + (n0 & 15)) * Sseq + ss) << 6) + (n0 >> 4);
                    const size_t i1 = (((size_t)(bb * Hn + ((n0 + 1) & 15)) * Sseq + ss) << 6) + ((n0 + 1) >> 4);
                    g_kh[i0] = h0; g_kl[i0] = l0;
                    g_kh[i1] = h1; g_kl[i1] = l1;
                } else {
                    if (z == 0) { v0 *= 0.125f; v1 *= 0.125f; }   // fold softmax scale
                    uint32_t hw, lw;
                    split2(v0, v1, hw, lw);
                    const size_t idx = (((size_t)(bb * Hn + (n0 >> 6)) * Sseq + ss) << 6) + (n0 & 63);
                    __nv_bfloat16* dh = (z == 0) ? g_qh : g_vh;
                    __nv_bfloat16* dl = (z == 0) ? g_ql : g_vl;
                    *(uint32_t*)(dh + idx) = hw;
                    *(uint32_t*)(dl + idx) = lw;
                }
            }
        }
    }
}

// ---------------------------------------------------------------------------
// Final projection: out = O @ Wp^T + bp  (f32 output)
// ---------------------------------------------------------------------------
__global__ __launch_bounds__(256, 2)
void out_gemm(const float* __restrict__ bias, float* __restrict__ Cout)
{
    extern __shared__ __align__(16) uint16_t dynsmem[];
    const uint32_t sb = smem_u32(dynsmem);

    const int tid  = threadIdx.x;
    const int lane = tid & 31;
    const int wid  = tid >> 5;
    const int wm   = wid >> 2;
    const int wn   = wid & 3;
    const int bm   = blockIdx.y * 128;
    const int bn   = blockIdx.x * 128;

    const int grp = lane >> 3, lr = lane & 7;
    const int baseA = (wm * 64 + (grp & 1) * 8 + lr) * SSTR + (grp >> 1) * 8;
    const int baseB = (wn * 32 + (grp >> 1) * 8 + lr) * SSTR + (grp & 1) * 8;

    float c4[4][4][4];
#pragma unroll
    for (int mt = 0; mt < 4; mt++)
#pragma unroll
        for (int nt = 0; nt < 4; nt++)
#pragma unroll
            for (int q = 0; q < 4; q++) c4[mt][nt][q] = 0.f;

    gemm_mainloop_pipe(c4, (const uint16_t*)g_oh, (const uint16_t*)g_ol,
                       (const uint16_t*)g_wph, (const uint16_t*)g_wpl,
                       sb, bm, bn, tid, baseA, baseB);

#pragma unroll
    for (int mt = 0; mt < 4; mt++) {
#pragma unroll
        for (int nt = 0; nt < 4; nt++) {
            const float* cc = c4[mt][nt];
            const int m0 = bm + wm * 64 + mt * 16 + (lane >> 2);
            const int n0 = bn + wn * 32 + nt * 8 + 2 * (lane & 3);
            const float b0 = __ldg(&bias[n0]);
            const float b1 = __ldg(&bias[n0 + 1]);
#pragma unroll
            for (int h = 0; h < 2; h++) {
                const int m = m0 + h * 8;
                *(float2*)(Cout + (size_t)m * Dm + n0) =
                    make_float2(cc[h * 2 + 0] + b0, cc[h * 2 + 1] + b1);
            }
        }
    }
}

// ---------------------------------------------------------------------------
// Flash attention via mma.sync bf16 hi/lo, cp.async double-buffered KV.
// Block = 128 thr / 4 warps; q-tile 64 (warp owns 16 rows), kv-tile 64.
// 3 CTAs/SM for softmax/MMA overlap across independent CTAs.
// Term-major MMA ordering (accumulator reuse distance 8).
// ---------------------------------------------------------------------------
constexpr int VSTR = 72;
constexpr int ABUF_E = 4 * 64 * VSTR;              // 18,432 elems per buffer
constexpr int ATTN_SMEM = 2 * ABUF_E * 2;          // 73,728 B

__global__ __launch_bounds__(128, 3)
void attn_mma()
{
    extern __shared__ __align__(16) uint16_t dynsmem[];
    uint16_t* sbuf = dynsmem;
    const int tid  = threadIdx.x;       // 0..127
    const int lane = tid & 31;
    const int w    = tid >> 5;          // 0..3
    const int qt   = (int)gridDim.x - 1 - (int)blockIdx.x;   // heavy blocks first
    const int bh   = blockIdx.y;
    const int grp  = lane >> 3, lr = lane & 7;
    const uint32_t sb = smem_u32(sbuf);

    // ---- stage Q hi/lo (64 rows) into buffer 0, load A-fragments ----
    const size_t qbase = ((size_t)bh * Sseq + (size_t)qt * 64) * 64;
#pragma unroll
    for (int i = 0; i < 4; i++) {
        const int idx = tid + i * 128;      // 0..511
        const int row = idx >> 3;           // 0..63
        const int c8  = (idx & 7) * 8;
        *(uint4*)&sbuf[row * VSTR + c8]        = *(const uint4*)((const uint16_t*)g_qh + qbase + row * 64 + c8);
        *(uint4*)&sbuf[9216 + row * VSTR + c8] = *(const uint4*)((const uint16_t*)g_ql + qbase + row * 64 + c8);
    }
    __syncthreads();
    uint32_t Qh[4][4], Ql[4][4];
#pragma unroll
    for (int ks = 0; ks < 4; ks++) {
        const int off = (w * 16 + (grp & 1) * 8 + lr) * VSTR + ks * 16 + (grp >> 1) * 8;
        ldmx4(Qh[ks], sb + (uint32_t)off * 2u);
        ldmx4(Ql[ks], sb + (uint32_t)(off + 9216) * 2u);
    }
    __syncthreads();   // Q reads done before kv overwrites buf0

    float O[8][4];
#pragma unroll
    for (int nt = 0; nt < 8; nt++)
#pragma unroll
        for (int q = 0; q < 4; q++) O[nt][q] = 0.f;
    float m_lo = -1e30f, m_hi = -1e30f, l_lo = 0.f, l_hi = 0.f;

    const int row_lo_g = qt * 64 + w * 16 + (lane >> 2);   // global q row (lo half)
    const size_t kvb0 = (size_t)bh * Sseq * 64;
    const int jmax = qt;

    auto issue_kv = [&](int j, int buf) {
        const size_t kb = kvb0 + (size_t)j * 64 * 64;
        const int boff = buf * ABUF_E;
#pragma unroll
        for (int i = 0; i < 4; i++) {
            const int idx = tid + i * 128;      // 0..511
            const int row = idx >> 3;
            const int c8  = (idx & 7) * 8;
            const int so  = row * VSTR + c8;
            const size_t go = kb + row * 64 + c8;
            CP_ASYNC16(sb + (uint32_t)(boff + so) * 2u,          (const uint16_t*)g_kh + go);
            CP_ASYNC16(sb + (uint32_t)(boff + 4608 + so) * 2u,   (const uint16_t*)g_kl + go);
            CP_ASYNC16(sb + (uint32_t)(boff + 9216 + so) * 2u,   (const uint16_t*)g_vh + go);
            CP_ASYNC16(sb + (uint32_t)(boff + 13824 + so) * 2u,  (const uint16_t*)g_vl + go);
        }
        CP_COMMIT();
    };

    issue_kv(0, 0);

    for (int j = 0; j <= jmax; j++) {
        const int buf = j & 1;
        if (j + 1 <= jmax) { issue_kv(j + 1, buf ^ 1); CP_WAIT1(); }
        else               { CP_WAIT0(); }
        __syncthreads();
        const uint32_t boff = (uint32_t)(buf * ABUF_E);

        // ---- S = Q @ K^T (hi/lo 3-term, term-major) ----
        float S[8][4];
#pragma unroll
        for (int nt = 0; nt < 8; nt++)
#pragma unroll
            for (int q = 0; q < 4; q++) S[nt][q] = 0.f;

#pragma unroll
        for (int ks = 0; ks < 4; ks++) {
            uint32_t KBh[16], KBl[16];
#pragma unroll
            for (int np = 0; np < 4; np++) {
                const uint32_t off = boff + (uint32_t)((np * 16 + (grp >> 1) * 8 + lr) * VSTR + ks * 16 + (grp & 1) * 8);
                ldmx4(&KBh[np * 4], sb + off * 2u);
                ldmx4(&KBl[np * 4], sb + (off + 4608u) * 2u);
            }
#pragma unroll
            for (int np = 0; np < 4; np++) {
                mma_bf16(S[np * 2],     Qh[ks], &KBh[np * 4]);
                mma_bf16(S[np * 2 + 1], Qh[ks], &KBh[np * 4 + 2]);
            }
#pragma unroll
            for (int np = 0; np < 4; np++) {
                mma_bf16(S[np * 2],     Qh[ks], &KBl[np * 4]);
                mma_bf16(S[np * 2 + 1], Qh[ks], &KBl[np * 4 + 2]);
            }
#pragma unroll
            for (int np = 0; np < 4; np++) {
                mma_bf16(S[np * 2],     Ql[ks], &KBh[np * 4]);
                mma_bf16(S[np * 2 + 1], Ql[ks], &KBh[np * 4 + 2]);
            }
        }

        // ---- causal mask (diagonal tile only) ----
        if (j == qt) {
#pragma unroll
            for (int nt = 0; nt < 8; nt++)
#pragma unroll
                for (int q = 0; q < 4; q++) {
                    const int col = j * 64 + nt * 8 + 2 * (lane & 3) + (q & 1);
                    const int row = row_lo_g + (q >> 1) * 8;
                    if (col > row) S[nt][q] = -1e30f;
                }
        }

        // ---- online softmax ----
        float vlo = -1e30f, vhi = -1e30f;
#pragma unroll
        for (int nt = 0; nt < 8; nt++) {
            vlo = fmaxf(vlo, fmaxf(S[nt][0], S[nt][1]));
            vhi = fmaxf(vhi, fmaxf(S[nt][2], S[nt][3]));
        }
        vlo = fmaxf(vlo, __shfl_xor_sync(0xffffffffu, vlo, 1));
        vlo = fmaxf(vlo, __shfl_xor_sync(0xffffffffu, vlo, 2));
        vhi = fmaxf(vhi, __shfl_xor_sync(0xffffffffu, vhi, 1));
        vhi = fmaxf(vhi, __shfl_xor_sync(0xffffffffu, vhi, 2));

        const float mn_lo = fmaxf(m_lo, vlo);
        const float mn_hi = fmaxf(m_hi, vhi);
        const float al = __expf(m_lo - mn_lo);
        const float ah = __expf(m_hi - mn_hi);
        m_lo = mn_lo; m_hi = mn_hi;

        float slo = 0.f, shi = 0.f;
#pragma unroll
        for (int nt = 0; nt < 8; nt++) {
            S[nt][0] = __expf(S[nt][0] - mn_lo);
            S[nt][1] = __expf(S[nt][1] - mn_lo);
            S[nt][2] = __expf(S[nt][2] - mn_hi);
            S[nt][3] = __expf(S[nt][3] - mn_hi);
            slo += S[nt][0] + S[nt][1];
            shi += S[nt][2] + S[nt][3];
        }
        slo += __shfl_xor_sync(0xffffffffu, slo, 1);
        slo += __shfl_xor_sync(0xffffffffu, slo, 2);
        shi += __shfl_xor_sync(0xffffffffu, shi, 1);
        shi += __shfl_xor_sync(0xffffffffu, shi, 2);
        l_lo = l_lo * al + slo;
        l_hi = l_hi * ah + shi;
#pragma unroll
        for (int nt = 0; nt < 8; nt++) {
            O[nt][0] *= al; O[nt][1] *= al;
            O[nt][2] *= ah; O[nt][3] *= ah;
        }

        // ---- O += P @ V (term-major) ----
#pragma unroll
        for (int ks = 0; ks < 4; ks++) {
            uint32_t Ph[4], Pl[4];
            split2(S[2 * ks][0], S[2 * ks][1], Ph[0], Pl[0]);
            split2(S[2 * ks][2], S[2 * ks][3], Ph[1], Pl[1]);
            split2(S[2 * ks + 1][0], S[2 * ks + 1][1], Ph[2], Pl[2]);
            split2(S[2 * ks + 1][2], S[2 * ks + 1][3], Ph[3], Pl[3]);
            uint32_t VBh[16], VBl[16];
#pragma unroll
            for (int np = 0; np < 4; np++) {
                const uint32_t off = boff + (uint32_t)((ks * 16 + (grp & 1) * 8 + lr) * VSTR + np * 16 + (grp >> 1) * 8);
                ldmx4t(&VBh[np * 4], sb + (off + 9216u) * 2u);
                ldmx4t(&VBl[np * 4], sb + (off + 13824u) * 2u);
            }
#pragma unroll
            for (int np = 0; np < 4; np++) {
                mma_bf16(O[np * 2],     Ph, &VBh[np * 4]);
                mma_bf16(O[np * 2 + 1], Ph, &VBh[np * 4 + 2]);
            }
#pragma unroll
            for (int np = 0; np < 4; np++) {
                mma_bf16(O[np * 2],     Ph, &VBl[np * 4]);
                mma_bf16(O[np * 2 + 1], Ph, &VBl[np * 4 + 2]);
            }
#pragma unroll
            for (int np = 0; np < 4; np++) {
                mma_bf16(O[np * 2],     Pl, &VBh[np * 4]);
                mma_bf16(O[np * 2 + 1], Pl, &VBh[np * 4 + 2]);
            }
        }
        __syncthreads();   // protects buf reuse by the next issue
    }

    // ---- epilogue: normalize, split to bf16 hi/lo, write [B,S,D] ----
    const float inv_lo = 1.0f / l_lo;
    const float inv_hi = 1.0f / l_hi;
    const int bb = bh >> 4, hh = bh & 15;
    const int col0 = hh * 64 + 2 * (lane & 3);
#pragma unroll
    for (int nt = 0; nt < 8; nt++) {
        const int col = col0 + nt * 8;
        uint32_t hw, lw;
        split2(O[nt][0] * inv_lo, O[nt][1] * inv_lo, hw, lw);
        const size_t i0 = ((size_t)bb * Sseq + row_lo_g) * Dm + col;
        *(uint32_t*)(g_oh + i0) = hw;
        *(uint32_t*)(g_ol + i0) = lw;
        split2(O[nt][2] * inv_hi, O[nt][3] * inv_hi, hw, lw);
        const size_t i1 = ((size_t)bb * Sseq + row_lo_g + 8) * Dm + col;
        *(uint32_t*)(g_oh + i1) = hw;
        *(uint32_t*)(g_ol + i1) = lw;
    }
}

// ---------------------------------------------------------------------------
// Launch
// ---------------------------------------------------------------------------
extern "C" void kernel_launch(void* const* d_in, const int* in_sizes, int n_in,
                              void* d_out, int out_size)
{
    const float* x  = (const float*)d_in[0];
    const float* Wq = (const float*)d_in[1];
    const float* bq = (const float*)d_in[2];
    const float* Wk = (const float*)d_in[3];
    const float* bk = (const float*)d_in[4];
    const float* Wv = (const float*)d_in[5];
    const float* bv = (const float*)d_in[6];
    const float* Wp = (const float*)d_in[7];
    const float* bp = (const float*)d_in[8];
    float* out = (float*)d_out;

    cudaFuncSetAttribute(qkv_gemm, cudaFuncAttributeMaxDynamicSharedMemorySize, GEMM_SMEM);
    cudaFuncSetAttribute(out_gemm, cudaFuncAttributeMaxDynamicSharedMemorySize, GEMM_SMEM);
    cudaFuncSetAttribute(attn_mma, cudaFuncAttributeMaxDynamicSharedMemorySize, ATTN_SMEM);

    // one-shot hi/lo splits (dest globals bound in device code)
    split_x<<<(int)(XSZ / 8 / 256), 256>>>(x);
    split_w4<<<dim3((int)(WSZ / 8 / 256), 4), 256>>>(Wq, Wk, Wv, Wp);

    qkv_gemm<<<dim3(Dm / 128, Mrows / 128, 3), 256, GEMM_SMEM>>>(bq, bk, bv);

    attn_mma<<<dim3(Sseq / 64, Bc * Hn), 128, ATTN_SMEM>>>();

    out_gemm<<<dim3(Dm / 128, Mrows / 128), 256, GEMM_SMEM>>>(bp, out);
}